// round 1
// baseline (speedup 1.0000x reference)
#include <cuda_runtime.h>
#include <cstdint>
#include <math.h>

// Problem constants (MiniMoE): B=4, S=2048, D=1024, E=8, d_ff=4096, top-2.
#define T_TOK   8192
#define D_DIM   1024
#define E_NUM   8
#define FF      4096
// Expert slot region: 2*T tokens plus per-expert 128-alignment padding.
#define EXP_CAP     17408            // 136 * 128  >= 16384 + 8*127
#define SHARED_BASE 17408
#define NSLOT       25600            // EXP_CAP + T_TOK (shared expert rows); 200*128

#define BM 128
#define BN 128
#define BK 16

// ---------------- scratch (static __device__, no allocation) ----------------
static __device__ int   g_slot_token [NSLOT];
static __device__ float g_slot_weight[NSLOT];
static __device__ int   g_slot_expert[NSLOT];
static __device__ int   g_counts[E_NUM];
static __device__ int   g_fill  [E_NUM];
static __device__ int   g_aoff  [E_NUM];
static __device__ int   g_tok_idx[T_TOK * 2];
static __device__ float g_tok_w  [T_TOK * 2];
static __device__ float g_h[(size_t)NSLOT * FF];   // 25600 x 4096 fp32 (~419MB)

// ---------------- init: default slots + zero counters ----------------
static __global__ void init_kernel() {
    int s = blockIdx.x * blockDim.x + threadIdx.x;
    if (s < NSLOT) {
        if (s < SHARED_BASE) {
            g_slot_token[s]  = -1;
            g_slot_weight[s] = 0.f;
            g_slot_expert[s] = 0;
        } else {
            g_slot_token[s]  = s - SHARED_BASE;  // shared expert: every token
            g_slot_weight[s] = 1.f;
            g_slot_expert[s] = E_NUM;            // 8 == shared
        }
    }
    if (s < E_NUM) { g_counts[s] = 0; g_fill[s] = 0; }
}

// ---------------- router: one warp per token ----------------
static __global__ void router_kernel(const float* __restrict__ x,
                                     const float* __restrict__ rw) {
    int gwarp = (blockIdx.x * blockDim.x + threadIdx.x) >> 5;
    int lane  = threadIdx.x & 31;
    if (gwarp >= T_TOK) return;

    const float* xr = x + (size_t)gwarp * D_DIM;
    float acc[E_NUM];
#pragma unroll
    for (int e = 0; e < E_NUM; e++) acc[e] = 0.f;

    for (int d = lane; d < D_DIM; d += 32) {
        float xv = xr[d];
#pragma unroll
        for (int e = 0; e < E_NUM; e++) acc[e] += xv * rw[e * D_DIM + d];
    }
#pragma unroll
    for (int e = 0; e < E_NUM; e++)
#pragma unroll
        for (int o = 16; o > 0; o >>= 1)
            acc[e] += __shfl_xor_sync(0xFFFFFFFFu, acc[e], o);

    if (lane == 0) {
        // top-1 (strict > keeps lowest index on ties, matching jax.lax.top_k)
        int i1 = 0; float l1 = acc[0];
#pragma unroll
        for (int e = 1; e < E_NUM; e++) if (acc[e] > l1) { l1 = acc[e]; i1 = e; }
        int i2 = -1; float l2 = -INFINITY;
#pragma unroll
        for (int e = 0; e < E_NUM; e++)
            if (e != i1 && acc[e] > l2) { l2 = acc[e]; i2 = e; }
        // renormalized top-2 softmax weights: softmax over {l1,l2}
        float w1 = 1.f / (1.f + expf(l2 - l1));
        float w2 = 1.f - w1;
        g_tok_idx[gwarp * 2 + 0] = i1;
        g_tok_idx[gwarp * 2 + 1] = i2;
        g_tok_w  [gwarp * 2 + 0] = w1;
        g_tok_w  [gwarp * 2 + 1] = w2;
        atomicAdd(&g_counts[i1], 1);
        atomicAdd(&g_counts[i2], 1);
    }
}

// ---------------- aligned prefix offsets ----------------
static __global__ void offsets_kernel() {
    if (blockIdx.x == 0 && threadIdx.x == 0) {
        int off = 0;
#pragma unroll
        for (int e = 0; e < E_NUM; e++) {
            g_aoff[e] = off;
            off = (off + g_counts[e] + 127) & ~127;
        }
    }
}

// ---------------- assign tokens to slots ----------------
static __global__ void assign_kernel() {
    int t = blockIdx.x * blockDim.x + threadIdx.x;
    if (t >= T_TOK) return;
#pragma unroll
    for (int k = 0; k < 2; k++) {
        int   e = g_tok_idx[t * 2 + k];
        float w = g_tok_w  [t * 2 + k];
        int pos = atomicAdd(&g_fill[e], 1);
        int s   = g_aoff[e] + pos;
        g_slot_token[s]  = t;
        g_slot_weight[s] = w;
        g_slot_expert[s] = e;
    }
}

// ---------------- zero output (out is poisoned / stale between replays) ----
static __global__ void zero_out_kernel(float4* __restrict__ out) {
    int i = blockIdx.x * blockDim.x + threadIdx.x;
    if (i < (T_TOK * D_DIM) / 4) out[i] = make_float4(0.f, 0.f, 0.f, 0.f);
}

// ---------------- fused ragged GEMM (fc+relu^2  OR  proj+weighted scatter) --
// IS_FC:  C[slot, n] = relu(sum_k A[tok, k] * W[e][n, k])^2  -> g_h
// !IS_FC: atomicAdd(out[tok, n], w * sum_k g_h[slot, k] * W[e][n, k])
template <int KDIM, bool IS_FC>
static __global__ void __launch_bounds__(256, 2)
moe_gemm(const float* __restrict__ A_x,     // fc: x ; proj: unused (uses g_h)
         const float* __restrict__ Wexp,    // [E][N][KDIM]
         const float* __restrict__ Wsh,     // [N][KDIM]
         float* __restrict__ outp)          // proj only
{
    __shared__ float As[BK][BM];
    __shared__ float Bs[BK][BN];

    const int m0  = blockIdx.y * BM;
    const int n0  = blockIdx.x * BN;
    const int tid = threadIdx.x;

    const int expert = g_slot_expert[m0];
    const int NDIM   = IS_FC ? FF : D_DIM;
    const float* __restrict__ Bmat =
        (expert < E_NUM) ? (Wexp + (size_t)expert * NDIM * KDIM) : Wsh;

    // load mapping: thread handles rows r0 and r0+64, quarter c4 of the K-tile
    const int r0    = tid >> 2;
    const int c4off = (tid & 3) * 4;

    const float* aptr[2];
#pragma unroll
    for (int i = 0; i < 2; i++) {
        int row  = r0 + i * 64;
        int slot = m0 + row;
        if (IS_FC) {
            int tok = g_slot_token[slot];
            aptr[i] = (tok >= 0) ? (A_x + (size_t)tok * D_DIM) : nullptr;
        } else {
            aptr[i] = &g_h[(size_t)slot * FF];
        }
    }
    const float* bptr[2];
#pragma unroll
    for (int i = 0; i < 2; i++)
        bptr[i] = Bmat + (size_t)(n0 + r0 + i * 64) * KDIM;

    const int ty = tid >> 4;   // 0..15 (m)
    const int tx = tid & 15;   // 0..15 (n)

    float acc[8][8];
#pragma unroll
    for (int ii = 0; ii < 8; ii++)
#pragma unroll
        for (int jj = 0; jj < 8; jj++) acc[ii][jj] = 0.f;

    for (int kk = 0; kk < KDIM; kk += BK) {
        float4 av[2], bv[2];
#pragma unroll
        for (int i = 0; i < 2; i++) {
            av[i] = aptr[i] ? *(const float4*)(aptr[i] + kk + c4off)
                            : make_float4(0.f, 0.f, 0.f, 0.f);
            bv[i] = *(const float4*)(bptr[i] + kk + c4off);
        }
        __syncthreads();
#pragma unroll
        for (int i = 0; i < 2; i++) {
            int row = r0 + i * 64;
            As[c4off + 0][row] = av[i].x;
            As[c4off + 1][row] = av[i].y;
            As[c4off + 2][row] = av[i].z;
            As[c4off + 3][row] = av[i].w;
            Bs[c4off + 0][row] = bv[i].x;
            Bs[c4off + 1][row] = bv[i].y;
            Bs[c4off + 2][row] = bv[i].z;
            Bs[c4off + 3][row] = bv[i].w;
        }
        __syncthreads();
#pragma unroll
        for (int k = 0; k < BK; k++) {
            float4 a0 = *(const float4*)&As[k][ty * 4];
            float4 a1 = *(const float4*)&As[k][ty * 4 + 64];
            float4 b0 = *(const float4*)&Bs[k][tx * 4];
            float4 b1 = *(const float4*)&Bs[k][tx * 4 + 64];
            float ar[8] = {a0.x, a0.y, a0.z, a0.w, a1.x, a1.y, a1.z, a1.w};
            float br[8] = {b0.x, b0.y, b0.z, b0.w, b1.x, b1.y, b1.z, b1.w};
#pragma unroll
            for (int ii = 0; ii < 8; ii++)
#pragma unroll
                for (int jj = 0; jj < 8; jj++)
                    acc[ii][jj] += ar[ii] * br[jj];
        }
    }

    // ------------- epilogue -------------
    if (IS_FC) {
#pragma unroll
        for (int ii = 0; ii < 8; ii++) {
            int row  = ty * 4 + (ii & 3) + (ii >> 2) * 64;
            int slot = m0 + row;
            float* hrow = &g_h[(size_t)slot * FF + n0];
#pragma unroll
            for (int jh = 0; jh < 2; jh++) {
                float4 v;
                float r0v = fmaxf(acc[ii][jh * 4 + 0], 0.f);
                float r1v = fmaxf(acc[ii][jh * 4 + 1], 0.f);
                float r2v = fmaxf(acc[ii][jh * 4 + 2], 0.f);
                float r3v = fmaxf(acc[ii][jh * 4 + 3], 0.f);
                v.x = r0v * r0v; v.y = r1v * r1v; v.z = r2v * r2v; v.w = r3v * r3v;
                *(float4*)(hrow + tx * 4 + jh * 64) = v;
            }
        }
    } else {
#pragma unroll
        for (int ii = 0; ii < 8; ii++) {
            int row  = ty * 4 + (ii & 3) + (ii >> 2) * 64;
            int slot = m0 + row;
            int tok  = g_slot_token[slot];
            float w  = g_slot_weight[slot];
            if (tok >= 0 && w != 0.f) {
                float* orow = outp + (size_t)tok * D_DIM + n0;
#pragma unroll
                for (int jj = 0; jj < 8; jj++) {
                    int col = tx * 4 + (jj & 3) + (jj >> 2) * 64;
                    atomicAdd(&orow[col], w * acc[ii][jj]);
                }
            }
        }
    }
}

// ---------------- launch ----------------
extern "C" void kernel_launch(void* const* d_in, const int* in_sizes, int n_in,
                              void* d_out, int out_size) {
    const float* x     = (const float*)d_in[0];   // [4,2048,1024]
    const float* rw    = (const float*)d_in[1];   // [8,1024]
    const float* wfc   = (const float*)d_in[2];   // [8,4096,1024]
    const float* wproj = (const float*)d_in[3];   // [8,1024,4096]
    const float* sfc   = (const float*)d_in[4];   // [4096,1024]
    const float* sproj = (const float*)d_in[5];   // [1024,4096]
    float* out = (float*)d_out;                   // [4,2048,1024] fp32

    init_kernel<<<(NSLOT + 255) / 256, 256>>>();
    router_kernel<<<T_TOK / 8, 256>>>(x, rw);     // 8 warps (tokens) per block
    offsets_kernel<<<1, 32>>>();
    assign_kernel<<<T_TOK / 256, 256>>>();
    zero_out_kernel<<<(T_TOK * D_DIM / 4 + 255) / 256, 256>>>((float4*)out);

    // fc + relu^2 : [25600 x 4096] = gathered_x[25600 x 1024] @ W^T
    moe_gemm<D_DIM, true><<<dim3(FF / BN, NSLOT / BM), 256>>>(x, wfc, sfc, nullptr);
    // proj + weighted scatter-add : out[tok] += w * (h[25600 x 4096] @ W^T)
    moe_gemm<FF, false><<<dim3(D_DIM / BN, NSLOT / BM), 256>>>(nullptr, wproj, sproj, out);
}

// round 3
// speedup vs baseline: 2.1513x; 2.1513x over previous
#include <cuda_runtime.h>
#include <cuda_bf16.h>
#include <cstdint>
#include <math.h>

// ---------------- problem constants ----------------
#define T_TOK   8192
#define D_DIM   1024
#define E_NUM   8
#define FF      4096
#define SHARED_BASE 17408
#define NSLOT       25600            // 200 * 128

#define BM  128
#define BN  128
#define BK  32
// smem tile: [128 rows][40 halves] padded stride (conflict-free ldmatrix)
#define SROW 40
#define TILE_HALVES (128 * SROW)     // 5120 halves = 10240 bytes
#define A_HI_B 0
#define A_LO_B (TILE_HALVES * 2)     // byte offsets
#define B_HI_B (TILE_HALVES * 4)
#define B_LO_B (TILE_HALVES * 6)

// ---------------- scratch (static __device__, no allocation) ----------------
static __device__ int   g_slot_token [NSLOT];
static __device__ float g_slot_weight[NSLOT];
static __device__ int   g_slot_expert[NSLOT];
static __device__ int   g_counts[E_NUM];
static __device__ int   g_fill  [E_NUM];
static __device__ int   g_aoff  [E_NUM];
static __device__ int   g_tok_idx[T_TOK * 2];
static __device__ float g_tok_w  [T_TOK * 2];
static __device__ __nv_bfloat16 g_h_hi[(size_t)NSLOT * FF];
static __device__ __nv_bfloat16 g_h_lo[(size_t)NSLOT * FF];

// ---------------- small helpers ----------------
__device__ __forceinline__ uint32_t smem_u32(const void* p) {
    uint32_t a;
    asm("{ .reg .u64 t; cvta.to.shared.u64 t, %1; cvt.u32.u64 %0, t; }" : "=r"(a) : "l"(p));
    return a;
}
__device__ __forceinline__ void ldm_x4(uint32_t addr, uint32_t r[4]) {
    asm volatile("ldmatrix.sync.aligned.m8n8.x4.shared.b16 {%0,%1,%2,%3}, [%4];"
                 : "=r"(r[0]), "=r"(r[1]), "=r"(r[2]), "=r"(r[3]) : "r"(addr));
}
__device__ __forceinline__ void mma16816(float d[4], const uint32_t a[4], const uint32_t b[2]) {
    asm volatile("mma.sync.aligned.m16n8k16.row.col.f32.bf16.bf16.f32 "
                 "{%0,%1,%2,%3}, {%4,%5,%6,%7}, {%8,%9}, {%0,%1,%2,%3};"
                 : "+f"(d[0]), "+f"(d[1]), "+f"(d[2]), "+f"(d[3])
                 : "r"(a[0]), "r"(a[1]), "r"(a[2]), "r"(a[3]), "r"(b[0]), "r"(b[1]));
}
// fp32x4 -> hi bf16x4 (uint2) + lo bf16x4 (uint2)
__device__ __forceinline__ void f4_hilo(float4 v, uint2& hi, uint2& lo) {
    __nv_bfloat162 h0 = __floats2bfloat162_rn(v.x, v.y);
    __nv_bfloat162 h1 = __floats2bfloat162_rn(v.z, v.w);
    float2 g0 = __bfloat1622float2(h0);
    float2 g1 = __bfloat1622float2(h1);
    __nv_bfloat162 l0 = __floats2bfloat162_rn(v.x - g0.x, v.y - g0.y);
    __nv_bfloat162 l1 = __floats2bfloat162_rn(v.z - g1.x, v.w - g1.y);
    hi.x = *reinterpret_cast<uint32_t*>(&h0);  hi.y = *reinterpret_cast<uint32_t*>(&h1);
    lo.x = *reinterpret_cast<uint32_t*>(&l0);  lo.y = *reinterpret_cast<uint32_t*>(&l1);
}

// ---------------- routing kernels ----------------
static __global__ void init_kernel() {
    int s = blockIdx.x * blockDim.x + threadIdx.x;
    if (s < NSLOT) {
        if (s < SHARED_BASE) {
            g_slot_token[s] = -1; g_slot_weight[s] = 0.f; g_slot_expert[s] = 0;
        } else {
            g_slot_token[s] = s - SHARED_BASE; g_slot_weight[s] = 1.f; g_slot_expert[s] = E_NUM;
        }
    }
    if (s < E_NUM) { g_counts[s] = 0; g_fill[s] = 0; }
}

static __global__ void router_kernel(const float* __restrict__ x,
                                     const float* __restrict__ rw) {
    int gwarp = (blockIdx.x * blockDim.x + threadIdx.x) >> 5;
    int lane  = threadIdx.x & 31;
    if (gwarp >= T_TOK) return;
    const float* xr = x + (size_t)gwarp * D_DIM;
    float acc[E_NUM];
#pragma unroll
    for (int e = 0; e < E_NUM; e++) acc[e] = 0.f;
    for (int d = lane; d < D_DIM; d += 32) {
        float xv = xr[d];
#pragma unroll
        for (int e = 0; e < E_NUM; e++) acc[e] += xv * rw[e * D_DIM + d];
    }
#pragma unroll
    for (int e = 0; e < E_NUM; e++)
#pragma unroll
        for (int o = 16; o > 0; o >>= 1)
            acc[e] += __shfl_xor_sync(0xFFFFFFFFu, acc[e], o);
    if (lane == 0) {
        int i1 = 0; float l1 = acc[0];
#pragma unroll
        for (int e = 1; e < E_NUM; e++) if (acc[e] > l1) { l1 = acc[e]; i1 = e; }
        int i2 = -1; float l2 = -INFINITY;
#pragma unroll
        for (int e = 0; e < E_NUM; e++)
            if (e != i1 && acc[e] > l2) { l2 = acc[e]; i2 = e; }
        float w1 = 1.f / (1.f + expf(l2 - l1));
        float w2 = 1.f - w1;
        g_tok_idx[gwarp * 2 + 0] = i1;  g_tok_idx[gwarp * 2 + 1] = i2;
        g_tok_w  [gwarp * 2 + 0] = w1;  g_tok_w  [gwarp * 2 + 1] = w2;
        atomicAdd(&g_counts[i1], 1);    atomicAdd(&g_counts[i2], 1);
    }
}

static __global__ void offsets_kernel() {
    if (blockIdx.x == 0 && threadIdx.x == 0) {
        int off = 0;
#pragma unroll
        for (int e = 0; e < E_NUM; e++) {
            g_aoff[e] = off;
            off = (off + g_counts[e] + 127) & ~127;
        }
    }
}

static __global__ void assign_kernel() {
    int t = blockIdx.x * blockDim.x + threadIdx.x;
    if (t >= T_TOK) return;
#pragma unroll
    for (int k = 0; k < 2; k++) {
        int   e = g_tok_idx[t * 2 + k];
        float w = g_tok_w  [t * 2 + k];
        int pos = atomicAdd(&g_fill[e], 1);
        int s   = g_aoff[e] + pos;
        g_slot_token[s] = t; g_slot_weight[s] = w; g_slot_expert[s] = e;
    }
}

static __global__ void zero_out_kernel(float4* __restrict__ out) {
    int i = blockIdx.x * blockDim.x + threadIdx.x;
    if (i < (T_TOK * D_DIM) / 4) out[i] = make_float4(0.f, 0.f, 0.f, 0.f);
}

// ---------------- mma.sync ragged GEMM (bf16x3 emulated fp32) ----------------
// IS_FC:  h = relu(gathered_x @ Wfc^T)^2 -> g_h_hi/lo
// !IS_FC: out[tok] += w * (g_h @ Wproj^T)
template <int KDIM, bool IS_FC>
static __global__ void __launch_bounds__(256, 1)
moe_mma(const float* __restrict__ xsrc,
        const float* __restrict__ Wexp,
        const float* __restrict__ Wsh,
        float* __restrict__ outp)
{
    __shared__ __align__(16) __nv_bfloat16 sm[TILE_HALVES * 4];
    const uint32_t sbase = smem_u32(sm);

    const int tid  = threadIdx.x;
    const int wid  = tid >> 5, lane = tid & 31;
    const int wm   = wid >> 1, wn = wid & 1;       // 4 x 2 warp grid
    const int m0   = blockIdx.y * BM, n0 = blockIdx.x * BN;
    const int expert = g_slot_expert[m0];
    const int NDIM = IS_FC ? FF : D_DIM;
    const float* __restrict__ Bmat =
        (expert < E_NUM) ? (Wexp + (size_t)expert * NDIM * KDIM) : Wsh;

    // ---- loader mapping: thread t covers rows (t>>3)+32p (p=0..3), k-quad t&7 ----
    const int lr = tid >> 3;
    const int lq = tid & 7;
    const float*         aF[4];
    const __nv_bfloat16* aH[4];
    const __nv_bfloat16* aL[4];
    const float*         bF[4];
#pragma unroll
    for (int p = 0; p < 4; p++) {
        int row  = lr + 32 * p;
        int slot = m0 + row;
        if (IS_FC) {
            int tok = g_slot_token[slot];
            aF[p] = (tok >= 0) ? xsrc + (size_t)tok * KDIM : nullptr;
        } else {
            aH[p] = g_h_hi + (size_t)slot * KDIM;
            aL[p] = g_h_lo + (size_t)slot * KDIM;
        }
        bF[p] = Bmat + (size_t)(n0 + row) * KDIM;
    }

    // ---- ldmatrix lane offsets (bytes within a tile) ----
    uint32_t a_off[2], b_off[4];
#pragma unroll
    for (int mt = 0; mt < 2; mt++) {
        int rowA = wm * 32 + mt * 16 + (lane & 15);
        a_off[mt] = (uint32_t)rowA * (SROW * 2) + (uint32_t)(lane >> 4) * 16;
    }
#pragma unroll
    for (int p = 0; p < 4; p++) {
        int rowB = wn * 64 + p * 16 + (lane & 7) + ((lane >> 4) << 3);
        b_off[p] = (uint32_t)rowB * (SROW * 2) + (uint32_t)((lane >> 3) & 1) * 16;
    }

    float acc[2][8][4];
#pragma unroll
    for (int mt = 0; mt < 2; mt++)
#pragma unroll
        for (int nt = 0; nt < 8; nt++)
#pragma unroll
            for (int j = 0; j < 4; j++) acc[mt][nt][j] = 0.f;

    // ---- staging registers ----
    float4 aSf[4], bSf[4];
    uint4  aSh[4];                      // GEMM2: {hi.x, hi.y, lo.x, lo.y}

    auto ld_stage = [&](int kc) {
        const int kb = kc * BK + lq * 4;
#pragma unroll
        for (int p = 0; p < 4; p++) {
            if (IS_FC) {
                aSf[p] = aF[p] ? *(const float4*)(aF[p] + kb)
                               : make_float4(0.f, 0.f, 0.f, 0.f);
            } else {
                uint2 h = *(const uint2*)(aH[p] + kb);
                uint2 l = *(const uint2*)(aL[p] + kb);
                aSh[p] = make_uint4(h.x, h.y, l.x, l.y);
            }
            bSf[p] = *(const float4*)(bF[p] + kb);
        }
    };

    auto sts_stage = [&]() {
#pragma unroll
        for (int p = 0; p < 4; p++) {
            int row = lr + 32 * p;
            uint32_t off = (uint32_t)row * SROW + (uint32_t)lq * 4;   // halves
            uint2 hi, lo;
            if (IS_FC) { f4_hilo(aSf[p], hi, lo); }
            else       { hi = make_uint2(aSh[p].x, aSh[p].y);
                         lo = make_uint2(aSh[p].z, aSh[p].w); }
            *(uint2*)((char*)sm + A_HI_B + off * 2) = hi;
            *(uint2*)((char*)sm + A_LO_B + off * 2) = lo;
            f4_hilo(bSf[p], hi, lo);
            *(uint2*)((char*)sm + B_HI_B + off * 2) = hi;
            *(uint2*)((char*)sm + B_LO_B + off * 2) = lo;
        }
    };

    const int NK = KDIM / BK;
    ld_stage(0);
    for (int kc = 0; kc < NK; kc++) {
        __syncthreads();               // previous chunk's MMA reads complete
        sts_stage();
        __syncthreads();
        if (kc + 1 < NK) ld_stage(kc + 1);   // LDG overlaps MMA below

#pragma unroll
        for (int kk = 0; kk < 2; kk++) {
            const uint32_t kb = (uint32_t)kk * 32;   // 16 halves
            uint32_t ah[2][4], al[2][4], bh[8][2], bl[8][2];
#pragma unroll
            for (int mt = 0; mt < 2; mt++) {
                ldm_x4(sbase + A_HI_B + a_off[mt] + kb, ah[mt]);
                ldm_x4(sbase + A_LO_B + a_off[mt] + kb, al[mt]);
            }
#pragma unroll
            for (int p = 0; p < 4; p++) {
                uint32_t t[4];
                ldm_x4(sbase + B_HI_B + b_off[p] + kb, t);
                bh[2*p][0] = t[0]; bh[2*p][1] = t[1];
                bh[2*p+1][0] = t[2]; bh[2*p+1][1] = t[3];
                ldm_x4(sbase + B_LO_B + b_off[p] + kb, t);
                bl[2*p][0] = t[0]; bl[2*p][1] = t[1];
                bl[2*p+1][0] = t[2]; bl[2*p+1][1] = t[3];
            }
#pragma unroll
            for (int mt = 0; mt < 2; mt++)
#pragma unroll
                for (int nt = 0; nt < 8; nt++) {
                    mma16816(acc[mt][nt], ah[mt], bh[nt]);
                    mma16816(acc[mt][nt], ah[mt], bl[nt]);
                    mma16816(acc[mt][nt], al[mt], bh[nt]);
                }
        }
    }

    // ---------------- epilogue ----------------
    const int qn = 2 * (lane & 3);
#pragma unroll
    for (int mt = 0; mt < 2; mt++) {
#pragma unroll
        for (int half = 0; half < 2; half++) {
            const int row  = wm * 32 + mt * 16 + (lane >> 2) + 8 * half;
            const int slot = m0 + row;
            if (IS_FC) {
                const size_t base = (size_t)slot * FF + n0 + wn * 64 + qn;
#pragma unroll
                for (int nt = 0; nt < 8; nt++) {
                    float v0 = fmaxf(acc[mt][nt][2 * half + 0], 0.f); v0 *= v0;
                    float v1 = fmaxf(acc[mt][nt][2 * half + 1], 0.f); v1 *= v1;
                    __nv_bfloat162 h = __floats2bfloat162_rn(v0, v1);
                    float2 g = __bfloat1622float2(h);
                    __nv_bfloat162 l = __floats2bfloat162_rn(v0 - g.x, v1 - g.y);
                    *(uint32_t*)&g_h_hi[base + nt * 8] = *reinterpret_cast<uint32_t*>(&h);
                    *(uint32_t*)&g_h_lo[base + nt * 8] = *reinterpret_cast<uint32_t*>(&l);
                }
            } else {
                const int   tok = g_slot_token[slot];
                const float w   = g_slot_weight[slot];
                if (tok >= 0 && w != 0.f) {
                    float* orow = outp + (size_t)tok * D_DIM + n0 + wn * 64 + qn;
#pragma unroll
                    for (int nt = 0; nt < 8; nt++) {
                        atomicAdd(orow + nt * 8 + 0, w * acc[mt][nt][2 * half + 0]);
                        atomicAdd(orow + nt * 8 + 1, w * acc[mt][nt][2 * half + 1]);
                    }
                }
            }
        }
    }
}

// ---------------- launch ----------------
extern "C" void kernel_launch(void* const* d_in, const int* in_sizes, int n_in,
                              void* d_out, int out_size) {
    const float* x     = (const float*)d_in[0];   // [4,2048,1024]
    const float* rw    = (const float*)d_in[1];   // [8,1024]
    const float* wfc   = (const float*)d_in[2];   // [8,4096,1024]
    const float* wproj = (const float*)d_in[3];   // [8,1024,4096]
    const float* sfc   = (const float*)d_in[4];   // [4096,1024]
    const float* sproj = (const float*)d_in[5];   // [1024,4096]
    float* out = (float*)d_out;                   // [4,2048,1024] fp32

    init_kernel<<<(NSLOT + 255) / 256, 256>>>();
    router_kernel<<<T_TOK / 8, 256>>>(x, rw);
    offsets_kernel<<<1, 32>>>();
    assign_kernel<<<T_TOK / 256, 256>>>();
    zero_out_kernel<<<(T_TOK * D_DIM / 4 + 255) / 256, 256>>>((float4*)out);

    // GEMM1: h = relu(gathered_x @ Wfc^T)^2
    moe_mma<D_DIM, true ><<<dim3(FF / BN,    NSLOT / BM), 256>>>(x, wfc, sfc, nullptr);
    // GEMM2: out += w * (h @ Wproj^T)
    moe_mma<FF,    false><<<dim3(D_DIM / BN, NSLOT / BM), 256>>>(nullptr, wproj, sproj, out);
}

// round 4
// speedup vs baseline: 2.5942x; 1.2059x over previous
#include <cuda_runtime.h>
#include <cuda_fp16.h>
#include <cstdint>
#include <math.h>

// ---------------- problem constants ----------------
#define T_TOK   8192
#define D_DIM   1024
#define E_NUM   8
#define FF      4096
#define SHARED_BASE 17408
#define NSLOT       25600            // 200 * 128

#define BM  128
#define BN  128
#define BK  64                        // halves per K-chunk (128 B per row)
#define TILE_B 16384                  // 128 rows * 128 B
#define A_HI 0
#define A_LO 16384
#define B_HI 32768
#define B_LO 49152
#define BUF_B 65536
#define SMEM_TOTAL 131072             // double-buffered

// ---------------- scratch (static __device__, no allocation) ----------------
static __device__ int   g_slot_token [NSLOT];
static __device__ float g_slot_weight[NSLOT];
static __device__ int   g_slot_expert[NSLOT];
static __device__ int   g_counts[E_NUM];
static __device__ int   g_fill  [E_NUM];
static __device__ int   g_aoff  [E_NUM];
static __device__ int   g_tok_idx[T_TOK * 2];
static __device__ float g_tok_w  [T_TOK * 2];

// fp16 hi/lo planes (pre-converted once per launch)
static __device__ __half g_x_hi    [(size_t)T_TOK * D_DIM];
static __device__ __half g_x_lo    [(size_t)T_TOK * D_DIM];
static __device__ __half g_wfc_hi  [(size_t)E_NUM * FF * D_DIM];
static __device__ __half g_wfc_lo  [(size_t)E_NUM * FF * D_DIM];
static __device__ __half g_wpj_hi  [(size_t)E_NUM * D_DIM * FF];
static __device__ __half g_wpj_lo  [(size_t)E_NUM * D_DIM * FF];
static __device__ __half g_sfc_hi  [(size_t)FF * D_DIM];
static __device__ __half g_sfc_lo  [(size_t)FF * D_DIM];
static __device__ __half g_spj_hi  [(size_t)D_DIM * FF];
static __device__ __half g_spj_lo  [(size_t)D_DIM * FF];
static __device__ __half g_h_hi    [(size_t)NSLOT * FF];
static __device__ __half g_h_lo    [(size_t)NSLOT * FF];

// ---------------- helpers ----------------
__device__ __forceinline__ uint32_t smem_u32(const void* p) {
    uint32_t a;
    asm("{ .reg .u64 t; cvta.to.shared.u64 t, %1; cvt.u32.u64 %0, t; }" : "=r"(a) : "l"(p));
    return a;
}
__device__ __forceinline__ void ldm_x4(uint32_t addr, uint32_t r[4]) {
    asm volatile("ldmatrix.sync.aligned.m8n8.x4.shared.b16 {%0,%1,%2,%3}, [%4];"
                 : "=r"(r[0]), "=r"(r[1]), "=r"(r[2]), "=r"(r[3]) : "r"(addr));
}
__device__ __forceinline__ void mma16816(float d[4], const uint32_t a[4], const uint32_t b[2]) {
    asm volatile("mma.sync.aligned.m16n8k16.row.col.f32.f16.f16.f32 "
                 "{%0,%1,%2,%3}, {%4,%5,%6,%7}, {%8,%9}, {%0,%1,%2,%3};"
                 : "+f"(d[0]), "+f"(d[1]), "+f"(d[2]), "+f"(d[3])
                 : "r"(a[0]), "r"(a[1]), "r"(a[2]), "r"(a[3]), "r"(b[0]), "r"(b[1]));
}
__device__ __forceinline__ void sts16(uint32_t addr, uint4 v) {
    asm volatile("st.shared.v4.b32 [%0], {%1,%2,%3,%4};"
                 :: "r"(addr), "r"(v.x), "r"(v.y), "r"(v.z), "r"(v.w) : "memory");
}

// ---------------- pre-convert fp32 -> fp16 hi/lo planes ----------------
static __global__ void cvt_plane(const float4* __restrict__ src,
                                 __half* __restrict__ hi, __half* __restrict__ lo,
                                 int n4) {
    int i = blockIdx.x * blockDim.x + threadIdx.x;
    if (i >= n4) return;
    float4 v = src[i];
    __half2 h0 = __floats2half2_rn(v.x, v.y);
    __half2 h1 = __floats2half2_rn(v.z, v.w);
    float2 f0 = __half22float2(h0);
    float2 f1 = __half22float2(h1);
    __half2 l0 = __floats2half2_rn(v.x - f0.x, v.y - f0.y);
    __half2 l1 = __floats2half2_rn(v.z - f1.x, v.w - f1.y);
    *(uint2*)(hi + 4 * (size_t)i) =
        make_uint2(*reinterpret_cast<uint32_t*>(&h0), *reinterpret_cast<uint32_t*>(&h1));
    *(uint2*)(lo + 4 * (size_t)i) =
        make_uint2(*reinterpret_cast<uint32_t*>(&l0), *reinterpret_cast<uint32_t*>(&l1));
}

// ---------------- routing kernels ----------------
static __global__ void init_kernel() {
    int s = blockIdx.x * blockDim.x + threadIdx.x;
    if (s < NSLOT) {
        if (s < SHARED_BASE) {
            g_slot_token[s] = -1; g_slot_weight[s] = 0.f; g_slot_expert[s] = 0;
        } else {
            g_slot_token[s] = s - SHARED_BASE; g_slot_weight[s] = 1.f; g_slot_expert[s] = E_NUM;
        }
    }
    if (s < E_NUM) { g_counts[s] = 0; g_fill[s] = 0; }
}

static __global__ void router_kernel(const float* __restrict__ x,
                                     const float* __restrict__ rw) {
    int gwarp = (blockIdx.x * blockDim.x + threadIdx.x) >> 5;
    int lane  = threadIdx.x & 31;
    if (gwarp >= T_TOK) return;
    const float* xr = x + (size_t)gwarp * D_DIM;
    float acc[E_NUM];
#pragma unroll
    for (int e = 0; e < E_NUM; e++) acc[e] = 0.f;
    for (int d = lane; d < D_DIM; d += 32) {
        float xv = xr[d];
#pragma unroll
        for (int e = 0; e < E_NUM; e++) acc[e] += xv * rw[e * D_DIM + d];
    }
#pragma unroll
    for (int e = 0; e < E_NUM; e++)
#pragma unroll
        for (int o = 16; o > 0; o >>= 1)
            acc[e] += __shfl_xor_sync(0xFFFFFFFFu, acc[e], o);
    if (lane == 0) {
        int i1 = 0; float l1 = acc[0];
#pragma unroll
        for (int e = 1; e < E_NUM; e++) if (acc[e] > l1) { l1 = acc[e]; i1 = e; }
        int i2 = -1; float l2 = -INFINITY;
#pragma unroll
        for (int e = 0; e < E_NUM; e++)
            if (e != i1 && acc[e] > l2) { l2 = acc[e]; i2 = e; }
        float w1 = 1.f / (1.f + expf(l2 - l1));
        float w2 = 1.f - w1;
        g_tok_idx[gwarp * 2 + 0] = i1;  g_tok_idx[gwarp * 2 + 1] = i2;
        g_tok_w  [gwarp * 2 + 0] = w1;  g_tok_w  [gwarp * 2 + 1] = w2;
        atomicAdd(&g_counts[i1], 1);    atomicAdd(&g_counts[i2], 1);
    }
}

static __global__ void offsets_kernel() {
    if (blockIdx.x == 0 && threadIdx.x == 0) {
        int off = 0;
#pragma unroll
        for (int e = 0; e < E_NUM; e++) {
            g_aoff[e] = off;
            off = (off + g_counts[e] + 127) & ~127;
        }
    }
}

static __global__ void assign_kernel() {
    int t = blockIdx.x * blockDim.x + threadIdx.x;
    if (t >= T_TOK) return;
#pragma unroll
    for (int k = 0; k < 2; k++) {
        int   e = g_tok_idx[t * 2 + k];
        float w = g_tok_w  [t * 2 + k];
        int pos = atomicAdd(&g_fill[e], 1);
        int s   = g_aoff[e] + pos;
        g_slot_token[s] = t; g_slot_weight[s] = w; g_slot_expert[s] = e;
    }
}

static __global__ void zero_out_kernel(float4* __restrict__ out) {
    int i = blockIdx.x * blockDim.x + threadIdx.x;
    if (i < (T_TOK * D_DIM) / 4) out[i] = make_float4(0.f, 0.f, 0.f, 0.f);
}

// ---------------- fp16x3 mma.sync ragged GEMM, double-buffered ----------------
// IS_FC:  h = relu(gathered_x @ Wfc^T)^2 -> g_h_hi/lo
// !IS_FC: out[tok] += w * (g_h @ Wproj^T)
template <int KDIM, bool IS_FC>
static __global__ void __launch_bounds__(256, 1)
moe_mma(float* __restrict__ outp)
{
    extern __shared__ __align__(16) char smem[];
    const uint32_t sb = smem_u32(smem);

    const int tid  = threadIdx.x;
    const int wid  = tid >> 5, lane = tid & 31;
    const int wm   = wid >> 1, wn = wid & 1;       // 4 x 2 warp grid
    const int m0   = blockIdx.y * BM, n0 = blockIdx.x * BN;
    const int expert = g_slot_expert[m0];

    // select operand planes
    const __half *Ah, *Al, *Bh, *Bl;
    if (IS_FC) {
        Ah = g_x_hi; Al = g_x_lo;
        if (expert < E_NUM) {
            Bh = g_wfc_hi + (size_t)expert * FF * D_DIM;
            Bl = g_wfc_lo + (size_t)expert * FF * D_DIM;
        } else { Bh = g_sfc_hi; Bl = g_sfc_lo; }
    } else {
        Ah = g_h_hi; Al = g_h_lo;
        if (expert < E_NUM) {
            Bh = g_wpj_hi + (size_t)expert * D_DIM * FF;
            Bl = g_wpj_lo + (size_t)expert * D_DIM * FF;
        } else { Bh = g_spj_hi; Bl = g_spj_lo; }
    }

    // ---- loader mapping: rows lr+32p (p=0..3), 16B col g ----
    const int lr = tid >> 3;
    const int g  = tid & 7;
    const __half* aHp[4]; const __half* aLp[4];
    const __half* bHp[4]; const __half* bLp[4];
    uint32_t soff[4];
#pragma unroll
    for (int p = 0; p < 4; p++) {
        int row  = lr + 32 * p;
        int slot = m0 + row;
        size_t abase;
        bool valid = true;
        if (IS_FC) {
            int tok = g_slot_token[slot];
            valid = (tok >= 0);
            abase = (size_t)(valid ? tok : 0) * KDIM;
        } else {
            abase = (size_t)slot * KDIM;
        }
        aHp[p] = valid ? Ah + abase : nullptr;
        aLp[p] = valid ? Al + abase : nullptr;
        bHp[p] = Bh + (size_t)(n0 + row) * KDIM;
        bLp[p] = Bl + (size_t)(n0 + row) * KDIM;
        soff[p] = (uint32_t)row * 128 + (((uint32_t)g * 16) ^ (((uint32_t)row & 7) * 16));
    }

    // ---- ldmatrix lane address parts (within tile, swizzled) ----
    uint32_t preA[2], xvA[2], preB[4], xvB[4];
    const uint32_t cA = ((uint32_t)lane >> 4) * 16;
    const uint32_t cB = (((uint32_t)lane >> 3) & 1) * 16;
#pragma unroll
    for (int mt = 0; mt < 2; mt++) {
        uint32_t rowA = wm * 32 + mt * 16 + (lane & 15);
        preA[mt] = rowA * 128;
        xvA[mt]  = (rowA & 7) * 16;
    }
#pragma unroll
    for (int p = 0; p < 4; p++) {
        uint32_t rowB = wn * 64 + p * 16 + (lane & 7) + (((uint32_t)lane >> 4) << 3);
        preB[p] = rowB * 128;
        xvB[p]  = (rowB & 7) * 16;
    }

    float acc[2][8][4];
#pragma unroll
    for (int mt = 0; mt < 2; mt++)
#pragma unroll
        for (int nt = 0; nt < 8; nt++)
#pragma unroll
            for (int j = 0; j < 4; j++) acc[mt][nt][j] = 0.f;

    uint4 sAh[4], sAl[4], sBh[4], sBl[4];

    auto ldg_stage = [&](int kc) {
        const int kb = kc * BK + g * 8;
#pragma unroll
        for (int p = 0; p < 4; p++) {
            sAh[p] = aHp[p] ? *(const uint4*)(aHp[p] + kb) : make_uint4(0, 0, 0, 0);
            sAl[p] = aLp[p] ? *(const uint4*)(aLp[p] + kb) : make_uint4(0, 0, 0, 0);
            sBh[p] = *(const uint4*)(bHp[p] + kb);
            sBl[p] = *(const uint4*)(bLp[p] + kb);
        }
    };
    auto sts_stage = [&](uint32_t bb) {
#pragma unroll
        for (int p = 0; p < 4; p++) {
            sts16(bb + A_HI + soff[p], sAh[p]);
            sts16(bb + A_LO + soff[p], sAl[p]);
            sts16(bb + B_HI + soff[p], sBh[p]);
            sts16(bb + B_LO + soff[p], sBl[p]);
        }
    };
    auto mma_chunk = [&](uint32_t bb) {
#pragma unroll
        for (int kk = 0; kk < 4; kk++) {
            const uint32_t kb = (uint32_t)kk * 32;
            uint32_t ah[2][4], al[2][4], bh[8][2], bl[8][2];
#pragma unroll
            for (int mt = 0; mt < 2; mt++) {
                ldm_x4(bb + A_HI + preA[mt] + ((cA + kb) ^ xvA[mt]), ah[mt]);
                ldm_x4(bb + A_LO + preA[mt] + ((cA + kb) ^ xvA[mt]), al[mt]);
            }
#pragma unroll
            for (int p = 0; p < 4; p++) {
                uint32_t t[4];
                ldm_x4(bb + B_HI + preB[p] + ((cB + kb) ^ xvB[p]), t);
                bh[2*p][0] = t[0]; bh[2*p][1] = t[1];
                bh[2*p+1][0] = t[2]; bh[2*p+1][1] = t[3];
                ldm_x4(bb + B_LO + preB[p] + ((cB + kb) ^ xvB[p]), t);
                bl[2*p][0] = t[0]; bl[2*p][1] = t[1];
                bl[2*p+1][0] = t[2]; bl[2*p+1][1] = t[3];
            }
#pragma unroll
            for (int mt = 0; mt < 2; mt++)
#pragma unroll
                for (int nt = 0; nt < 8; nt++) {
                    mma16816(acc[mt][nt], ah[mt], bh[nt]);
                    mma16816(acc[mt][nt], ah[mt], bl[nt]);
                    mma16816(acc[mt][nt], al[mt], bh[nt]);
                }
        }
    };

    const int NK = KDIM / BK;
    ldg_stage(0);
    sts_stage(sb);
    __syncthreads();
    for (int kc = 0; kc < NK; kc++) {
        if (kc + 1 < NK) ldg_stage(kc + 1);
        mma_chunk(sb + (kc & 1) * BUF_B);
        if (kc + 1 < NK) {
            sts_stage(sb + ((kc + 1) & 1) * BUF_B);
            __syncthreads();
        }
    }

    // ---------------- epilogue ----------------
    const int qn = 2 * (lane & 3);
#pragma unroll
    for (int mt = 0; mt < 2; mt++) {
#pragma unroll
        for (int half = 0; half < 2; half++) {
            const int row  = wm * 32 + mt * 16 + (lane >> 2) + 8 * half;
            const int slot = m0 + row;
            if (IS_FC) {
                const size_t base = (size_t)slot * FF + n0 + wn * 64 + qn;
#pragma unroll
                for (int nt = 0; nt < 8; nt++) {
                    float v0 = fmaxf(acc[mt][nt][2 * half + 0], 0.f); v0 *= v0;
                    float v1 = fmaxf(acc[mt][nt][2 * half + 1], 0.f); v1 *= v1;
                    __half2 h = __floats2half2_rn(v0, v1);
                    float2 f = __half22float2(h);
                    __half2 l = __floats2half2_rn(v0 - f.x, v1 - f.y);
                    *(uint32_t*)&g_h_hi[base + nt * 8] = *reinterpret_cast<uint32_t*>(&h);
                    *(uint32_t*)&g_h_lo[base + nt * 8] = *reinterpret_cast<uint32_t*>(&l);
                }
            } else {
                const int   tok = g_slot_token[slot];
                const float w   = g_slot_weight[slot];
                if (tok >= 0 && w != 0.f) {
                    float* orow = outp + (size_t)tok * D_DIM + n0 + wn * 64 + qn;
#pragma unroll
                    for (int nt = 0; nt < 8; nt++) {
                        atomicAdd(orow + nt * 8 + 0, w * acc[mt][nt][2 * half + 0]);
                        atomicAdd(orow + nt * 8 + 1, w * acc[mt][nt][2 * half + 1]);
                    }
                }
            }
        }
    }
}

// ---------------- launch ----------------
extern "C" void kernel_launch(void* const* d_in, const int* in_sizes, int n_in,
                              void* d_out, int out_size) {
    const float* x     = (const float*)d_in[0];   // [4,2048,1024]
    const float* rw    = (const float*)d_in[1];   // [8,1024]
    const float* wfc   = (const float*)d_in[2];   // [8,4096,1024]
    const float* wproj = (const float*)d_in[3];   // [8,1024,4096]
    const float* sfc   = (const float*)d_in[4];   // [4096,1024]
    const float* sproj = (const float*)d_in[5];   // [1024,4096]
    float* out = (float*)d_out;                   // [4,2048,1024] fp32

    cudaFuncSetAttribute(moe_mma<D_DIM, true>,
                         cudaFuncAttributeMaxDynamicSharedMemorySize, SMEM_TOTAL);
    cudaFuncSetAttribute(moe_mma<FF, false>,
                         cudaFuncAttributeMaxDynamicSharedMemorySize, SMEM_TOTAL);

    // pre-convert all operands to fp16 hi/lo planes
    __half *xh, *xl, *fh, *fl, *ph, *pl, *sh, *sl, *qh, *ql;
    cudaGetSymbolAddress((void**)&xh, g_x_hi);   cudaGetSymbolAddress((void**)&xl, g_x_lo);
    cudaGetSymbolAddress((void**)&fh, g_wfc_hi); cudaGetSymbolAddress((void**)&fl, g_wfc_lo);
    cudaGetSymbolAddress((void**)&ph, g_wpj_hi); cudaGetSymbolAddress((void**)&pl, g_wpj_lo);
    cudaGetSymbolAddress((void**)&sh, g_sfc_hi); cudaGetSymbolAddress((void**)&sl, g_sfc_lo);
    cudaGetSymbolAddress((void**)&qh, g_spj_hi); cudaGetSymbolAddress((void**)&ql, g_spj_lo);

    const int n4_x  = T_TOK * D_DIM / 4;
    const int n4_w  = E_NUM * FF * D_DIM / 4;
    const int n4_s  = FF * D_DIM / 4;
    cvt_plane<<<(n4_x + 255) / 256, 256>>>((const float4*)x,     xh, xl, n4_x);
    cvt_plane<<<(n4_w + 255) / 256, 256>>>((const float4*)wfc,   fh, fl, n4_w);
    cvt_plane<<<(n4_w + 255) / 256, 256>>>((const float4*)wproj, ph, pl, n4_w);
    cvt_plane<<<(n4_s + 255) / 256, 256>>>((const float4*)sfc,   sh, sl, n4_s);
    cvt_plane<<<(n4_s + 255) / 256, 256>>>((const float4*)sproj, qh, ql, n4_s);

    init_kernel<<<(NSLOT + 255) / 256, 256>>>();
    router_kernel<<<T_TOK / 8, 256>>>(x, rw);
    offsets_kernel<<<1, 32>>>();
    assign_kernel<<<T_TOK / 256, 256>>>();
    zero_out_kernel<<<(T_TOK * D_DIM / 4 + 255) / 256, 256>>>((float4*)out);

    // GEMM1: h = relu(gathered_x @ Wfc^T)^2
    moe_mma<D_DIM, true ><<<dim3(FF / BN,    NSLOT / BM), 256, SMEM_TOTAL>>>(nullptr);
    // GEMM2: out += w * (h @ Wproj^T)
    moe_mma<FF,    false><<<dim3(D_DIM / BN, NSLOT / BM), 256, SMEM_TOTAL>>>(out);
}

// round 5
// speedup vs baseline: 2.7330x; 1.0535x over previous
#include <cuda_runtime.h>
#include <cuda_fp16.h>
#include <cstdint>
#include <math.h>

// ---------------- problem constants ----------------
#define T_TOK   8192
#define D_DIM   1024
#define E_NUM   8
#define FF      4096
#define SHARED_BASE 17408
#define NSLOT       25600            // 200 * 128

#define BM  128
#define BN  128
#define BK  64                        // halves per K-chunk (128 B per row)
#define TILE_B 16384                  // 128 rows * 128 B
#define A_HI 0
#define A_LO 16384
#define B_HI 32768
#define B_LO 49152
#define BUF_B 65536
#define STAGES 3
#define SMEM_TOTAL (STAGES * BUF_B)   // 196608

// ---------------- scratch (static __device__, no allocation) ----------------
static __device__ int   g_slot_token [NSLOT];
static __device__ float g_slot_weight[NSLOT];
static __device__ int   g_slot_expert[NSLOT];
static __device__ int   g_counts[E_NUM];
static __device__ int   g_fill  [E_NUM];
static __device__ int   g_aoff  [E_NUM];
static __device__ int   g_tok_idx[T_TOK * 2];
static __device__ float g_tok_w  [T_TOK * 2];

// fp16 hi/lo planes (pre-converted once per launch)
static __device__ __half g_x_hi    [(size_t)T_TOK * D_DIM];
static __device__ __half g_x_lo    [(size_t)T_TOK * D_DIM];
static __device__ __half g_wfc_hi  [(size_t)E_NUM * FF * D_DIM];
static __device__ __half g_wfc_lo  [(size_t)E_NUM * FF * D_DIM];
static __device__ __half g_wpj_hi  [(size_t)E_NUM * D_DIM * FF];
static __device__ __half g_wpj_lo  [(size_t)E_NUM * D_DIM * FF];
static __device__ __half g_sfc_hi  [(size_t)FF * D_DIM];
static __device__ __half g_sfc_lo  [(size_t)FF * D_DIM];
static __device__ __half g_spj_hi  [(size_t)D_DIM * FF];
static __device__ __half g_spj_lo  [(size_t)D_DIM * FF];
static __device__ __half g_h_hi    [(size_t)NSLOT * FF];
static __device__ __half g_h_lo    [(size_t)NSLOT * FF];

// ---------------- helpers ----------------
__device__ __forceinline__ uint32_t smem_u32(const void* p) {
    uint32_t a;
    asm("{ .reg .u64 t; cvta.to.shared.u64 t, %1; cvt.u32.u64 %0, t; }" : "=r"(a) : "l"(p));
    return a;
}
__device__ __forceinline__ void ldm_x4(uint32_t addr, uint32_t r[4]) {
    asm volatile("ldmatrix.sync.aligned.m8n8.x4.shared.b16 {%0,%1,%2,%3}, [%4];"
                 : "=r"(r[0]), "=r"(r[1]), "=r"(r[2]), "=r"(r[3]) : "r"(addr));
}
__device__ __forceinline__ void mma16816(float d[4], const uint32_t a[4], const uint32_t b[2]) {
    asm volatile("mma.sync.aligned.m16n8k16.row.col.f32.f16.f16.f32 "
                 "{%0,%1,%2,%3}, {%4,%5,%6,%7}, {%8,%9}, {%0,%1,%2,%3};"
                 : "+f"(d[0]), "+f"(d[1]), "+f"(d[2]), "+f"(d[3])
                 : "r"(a[0]), "r"(a[1]), "r"(a[2]), "r"(a[3]), "r"(b[0]), "r"(b[1]));
}
// cp.async 16B; src_sz = 16 (copy) or 0 (zero-fill destination)
__device__ __forceinline__ void cp16(uint32_t saddr, const void* gaddr, uint32_t src_sz) {
    asm volatile("cp.async.cg.shared.global [%0], [%1], 16, %2;"
                 :: "r"(saddr), "l"(gaddr), "r"(src_sz) : "memory");
}
__device__ __forceinline__ void cp_commit() {
    asm volatile("cp.async.commit_group;" ::: "memory");
}
template <int N>
__device__ __forceinline__ void cp_wait() {
    asm volatile("cp.async.wait_group %0;" :: "n"(N) : "memory");
}

// ---------------- pre-convert fp32 -> fp16 hi/lo planes ----------------
static __global__ void cvt_plane(const float4* __restrict__ src,
                                 __half* __restrict__ hi, __half* __restrict__ lo,
                                 int n4) {
    int i = blockIdx.x * blockDim.x + threadIdx.x;
    if (i >= n4) return;
    float4 v = src[i];
    __half2 h0 = __floats2half2_rn(v.x, v.y);
    __half2 h1 = __floats2half2_rn(v.z, v.w);
    float2 f0 = __half22float2(h0);
    float2 f1 = __half22float2(h1);
    __half2 l0 = __floats2half2_rn(v.x - f0.x, v.y - f0.y);
    __half2 l1 = __floats2half2_rn(v.z - f1.x, v.w - f1.y);
    *(uint2*)(hi + 4 * (size_t)i) =
        make_uint2(*reinterpret_cast<uint32_t*>(&h0), *reinterpret_cast<uint32_t*>(&h1));
    *(uint2*)(lo + 4 * (size_t)i) =
        make_uint2(*reinterpret_cast<uint32_t*>(&l0), *reinterpret_cast<uint32_t*>(&l1));
}

// ---------------- routing kernels ----------------
static __global__ void init_kernel() {
    int s = blockIdx.x * blockDim.x + threadIdx.x;
    if (s < NSLOT) {
        if (s < SHARED_BASE) {
            g_slot_token[s] = -1; g_slot_weight[s] = 0.f; g_slot_expert[s] = 0;
        } else {
            g_slot_token[s] = s - SHARED_BASE; g_slot_weight[s] = 1.f; g_slot_expert[s] = E_NUM;
        }
    }
    if (s < E_NUM) { g_counts[s] = 0; g_fill[s] = 0; }
}

static __global__ void router_kernel(const float* __restrict__ x,
                                     const float* __restrict__ rw) {
    int gwarp = (blockIdx.x * blockDim.x + threadIdx.x) >> 5;
    int lane  = threadIdx.x & 31;
    if (gwarp >= T_TOK) return;
    const float* xr = x + (size_t)gwarp * D_DIM;
    float acc[E_NUM];
#pragma unroll
    for (int e = 0; e < E_NUM; e++) acc[e] = 0.f;
    for (int d = lane; d < D_DIM; d += 32) {
        float xv = xr[d];
#pragma unroll
        for (int e = 0; e < E_NUM; e++) acc[e] += xv * rw[e * D_DIM + d];
    }
#pragma unroll
    for (int e = 0; e < E_NUM; e++)
#pragma unroll
        for (int o = 16; o > 0; o >>= 1)
            acc[e] += __shfl_xor_sync(0xFFFFFFFFu, acc[e], o);
    if (lane == 0) {
        int i1 = 0; float l1 = acc[0];
#pragma unroll
        for (int e = 1; e < E_NUM; e++) if (acc[e] > l1) { l1 = acc[e]; i1 = e; }
        int i2 = -1; float l2 = -INFINITY;
#pragma unroll
        for (int e = 0; e < E_NUM; e++)
            if (e != i1 && acc[e] > l2) { l2 = acc[e]; i2 = e; }
        float w1 = 1.f / (1.f + expf(l2 - l1));
        float w2 = 1.f - w1;
        g_tok_idx[gwarp * 2 + 0] = i1;  g_tok_idx[gwarp * 2 + 1] = i2;
        g_tok_w  [gwarp * 2 + 0] = w1;  g_tok_w  [gwarp * 2 + 1] = w2;
        atomicAdd(&g_counts[i1], 1);    atomicAdd(&g_counts[i2], 1);
    }
}

static __global__ void offsets_kernel() {
    if (blockIdx.x == 0 && threadIdx.x == 0) {
        int off = 0;
#pragma unroll
        for (int e = 0; e < E_NUM; e++) {
            g_aoff[e] = off;
            off = (off + g_counts[e] + 127) & ~127;
        }
    }
}

static __global__ void assign_kernel() {
    int t = blockIdx.x * blockDim.x + threadIdx.x;
    if (t >= T_TOK) return;
#pragma unroll
    for (int k = 0; k < 2; k++) {
        int   e = g_tok_idx[t * 2 + k];
        float w = g_tok_w  [t * 2 + k];
        int pos = atomicAdd(&g_fill[e], 1);
        int s   = g_aoff[e] + pos;
        g_slot_token[s] = t; g_slot_weight[s] = w; g_slot_expert[s] = e;
    }
}

static __global__ void zero_out_kernel(float4* __restrict__ out) {
    int i = blockIdx.x * blockDim.x + threadIdx.x;
    if (i < (T_TOK * D_DIM) / 4) out[i] = make_float4(0.f, 0.f, 0.f, 0.f);
}

// ---------------- fp16x3 mma.sync ragged GEMM, cp.async 3-stage ----------------
// IS_FC:  h = relu(gathered_x @ Wfc^T)^2 -> g_h_hi/lo
// !IS_FC: out[tok] += w * (g_h @ Wproj^T)
template <int KDIM, bool IS_FC>
static __global__ void __launch_bounds__(256, 1)
moe_mma(float* __restrict__ outp)
{
    extern __shared__ __align__(16) char smem[];
    const uint32_t sb = smem_u32(smem);

    const int tid  = threadIdx.x;
    const int wid  = tid >> 5, lane = tid & 31;
    const int wm   = wid >> 1, wn = wid & 1;       // 4 x 2 warp grid
    const int m0   = blockIdx.y * BM, n0 = blockIdx.x * BN;
    const int expert = g_slot_expert[m0];

    // select operand planes
    const __half *Ah, *Al, *Bh, *Bl;
    if (IS_FC) {
        Ah = g_x_hi; Al = g_x_lo;
        if (expert < E_NUM) {
            Bh = g_wfc_hi + (size_t)expert * FF * D_DIM;
            Bl = g_wfc_lo + (size_t)expert * FF * D_DIM;
        } else { Bh = g_sfc_hi; Bl = g_sfc_lo; }
    } else {
        Ah = g_h_hi; Al = g_h_lo;
        if (expert < E_NUM) {
            Bh = g_wpj_hi + (size_t)expert * D_DIM * FF;
            Bl = g_wpj_lo + (size_t)expert * D_DIM * FF;
        } else { Bh = g_spj_hi; Bl = g_spj_lo; }
    }

    // ---- loader mapping: rows lr+32p (p=0..3), 16B col g ----
    const int lr = tid >> 3;
    const int g  = tid & 7;
    const __half* aHp[4]; const __half* aLp[4];
    const __half* bHp[4]; const __half* bLp[4];
    uint32_t asz[4];                    // 16 = copy, 0 = zero-fill (padding rows)
    uint32_t soff[4];
#pragma unroll
    for (int p = 0; p < 4; p++) {
        int row  = lr + 32 * p;
        int slot = m0 + row;
        size_t abase = 0;
        uint32_t sz = 16;
        if (IS_FC) {
            int tok = g_slot_token[slot];
            if (tok >= 0) abase = (size_t)tok * KDIM; else sz = 0;
        } else {
            abase = (size_t)slot * KDIM;
        }
        asz[p] = sz;
        aHp[p] = Ah + abase;
        aLp[p] = Al + abase;
        bHp[p] = Bh + (size_t)(n0 + row) * KDIM;
        bLp[p] = Bl + (size_t)(n0 + row) * KDIM;
        soff[p] = (uint32_t)row * 128 + (((uint32_t)g * 16) ^ (((uint32_t)row & 7) * 16));
    }

    // ---- ldmatrix lane address parts (within tile, swizzled) ----
    uint32_t preA[2], xvA[2], preB[4], xvB[4];
    const uint32_t cA = ((uint32_t)lane >> 4) * 16;
    const uint32_t cB = (((uint32_t)lane >> 3) & 1) * 16;
#pragma unroll
    for (int mt = 0; mt < 2; mt++) {
        uint32_t rowA = wm * 32 + mt * 16 + (lane & 15);
        preA[mt] = rowA * 128;
        xvA[mt]  = (rowA & 7) * 16;
    }
#pragma unroll
    for (int p = 0; p < 4; p++) {
        uint32_t rowB = wn * 64 + p * 16 + (lane & 7) + (((uint32_t)lane >> 4) << 3);
        preB[p] = rowB * 128;
        xvB[p]  = (rowB & 7) * 16;
    }

    float acc[2][8][4];
#pragma unroll
    for (int mt = 0; mt < 2; mt++)
#pragma unroll
        for (int nt = 0; nt < 8; nt++)
#pragma unroll
            for (int j = 0; j < 4; j++) acc[mt][nt][j] = 0.f;

    auto issue_stage = [&](int kc) {
        const uint32_t bb = sb + (uint32_t)(kc % STAGES) * BUF_B;
        const int kb = kc * BK + g * 8;
#pragma unroll
        for (int p = 0; p < 4; p++) {
            cp16(bb + A_HI + soff[p], aHp[p] + kb, asz[p]);
            cp16(bb + A_LO + soff[p], aLp[p] + kb, asz[p]);
            cp16(bb + B_HI + soff[p], bHp[p] + kb, 16u);
            cp16(bb + B_LO + soff[p], bLp[p] + kb, 16u);
        }
    };

    auto mma_chunk = [&](uint32_t bb) {
#pragma unroll
        for (int kk = 0; kk < 4; kk++) {
            const uint32_t kb = (uint32_t)kk * 32;
            uint32_t ah[2][4], al[2][4], bh[8][2], bl[8][2];
#pragma unroll
            for (int mt = 0; mt < 2; mt++) {
                ldm_x4(bb + A_HI + preA[mt] + ((cA + kb) ^ xvA[mt]), ah[mt]);
                ldm_x4(bb + A_LO + preA[mt] + ((cA + kb) ^ xvA[mt]), al[mt]);
            }
#pragma unroll
            for (int p = 0; p < 4; p++) {
                uint32_t t[4];
                ldm_x4(bb + B_HI + preB[p] + ((cB + kb) ^ xvB[p]), t);
                bh[2*p][0] = t[0]; bh[2*p][1] = t[1];
                bh[2*p+1][0] = t[2]; bh[2*p+1][1] = t[3];
                ldm_x4(bb + B_LO + preB[p] + ((cB + kb) ^ xvB[p]), t);
                bl[2*p][0] = t[0]; bl[2*p][1] = t[1];
                bl[2*p+1][0] = t[2]; bl[2*p+1][1] = t[3];
            }
#pragma unroll
            for (int mt = 0; mt < 2; mt++)
#pragma unroll
                for (int nt = 0; nt < 8; nt++) {
                    mma16816(acc[mt][nt], ah[mt], bh[nt]);
                    mma16816(acc[mt][nt], ah[mt], bl[nt]);
                    mma16816(acc[mt][nt], al[mt], bh[nt]);
                }
        }
    };

    const int NK = KDIM / BK;
    // prologue: fill STAGES-1 stages
#pragma unroll
    for (int s = 0; s < STAGES - 1; s++) {
        issue_stage(s);
        cp_commit();
    }
    for (int kc = 0; kc < NK; kc++) {
        cp_wait<STAGES - 2>();          // stage kc arrived
        __syncthreads();                // all threads see it; prev MMA done
        if (kc + STAGES - 1 < NK) issue_stage(kc + STAGES - 1);
        cp_commit();                    // keep group count aligned
        mma_chunk(sb + (uint32_t)(kc % STAGES) * BUF_B);
    }

    // ---------------- epilogue ----------------
    const int qn = 2 * (lane & 3);
#pragma unroll
    for (int mt = 0; mt < 2; mt++) {
#pragma unroll
        for (int half = 0; half < 2; half++) {
            const int row  = wm * 32 + mt * 16 + (lane >> 2) + 8 * half;
            const int slot = m0 + row;
            if (IS_FC) {
                const size_t base = (size_t)slot * FF + n0 + wn * 64 + qn;
#pragma unroll
                for (int nt = 0; nt < 8; nt++) {
                    float v0 = fmaxf(acc[mt][nt][2 * half + 0], 0.f); v0 *= v0;
                    float v1 = fmaxf(acc[mt][nt][2 * half + 1], 0.f); v1 *= v1;
                    __half2 h = __floats2half2_rn(v0, v1);
                    float2 f = __half22float2(h);
                    __half2 l = __floats2half2_rn(v0 - f.x, v1 - f.y);
                    *(uint32_t*)&g_h_hi[base + nt * 8] = *reinterpret_cast<uint32_t*>(&h);
                    *(uint32_t*)&g_h_lo[base + nt * 8] = *reinterpret_cast<uint32_t*>(&l);
                }
            } else {
                const int   tok = g_slot_token[slot];
                const float w   = g_slot_weight[slot];
                if (tok >= 0 && w != 0.f) {
                    float* orow = outp + (size_t)tok * D_DIM + n0 + wn * 64 + qn;
#pragma unroll
                    for (int nt = 0; nt < 8; nt++) {
                        atomicAdd(orow + nt * 8 + 0, w * acc[mt][nt][2 * half + 0]);
                        atomicAdd(orow + nt * 8 + 1, w * acc[mt][nt][2 * half + 1]);
                    }
                }
            }
        }
    }
}

// ---------------- launch ----------------
extern "C" void kernel_launch(void* const* d_in, const int* in_sizes, int n_in,
                              void* d_out, int out_size) {
    const float* x     = (const float*)d_in[0];   // [4,2048,1024]
    const float* rw    = (const float*)d_in[1];   // [8,1024]
    const float* wfc   = (const float*)d_in[2];   // [8,4096,1024]
    const float* wproj = (const float*)d_in[3];   // [8,1024,4096]
    const float* sfc   = (const float*)d_in[4];   // [4096,1024]
    const float* sproj = (const float*)d_in[5];   // [1024,4096]
    float* out = (float*)d_out;                   // [4,2048,1024] fp32

    cudaFuncSetAttribute(moe_mma<D_DIM, true>,
                         cudaFuncAttributeMaxDynamicSharedMemorySize, SMEM_TOTAL);
    cudaFuncSetAttribute(moe_mma<FF, false>,
                         cudaFuncAttributeMaxDynamicSharedMemorySize, SMEM_TOTAL);

    // pre-convert all operands to fp16 hi/lo planes
    __half *xh, *xl, *fh, *fl, *ph, *pl, *sh, *sl, *qh, *ql;
    cudaGetSymbolAddress((void**)&xh, g_x_hi);   cudaGetSymbolAddress((void**)&xl, g_x_lo);
    cudaGetSymbolAddress((void**)&fh, g_wfc_hi); cudaGetSymbolAddress((void**)&fl, g_wfc_lo);
    cudaGetSymbolAddress((void**)&ph, g_wpj_hi); cudaGetSymbolAddress((void**)&pl, g_wpj_lo);
    cudaGetSymbolAddress((void**)&sh, g_sfc_hi); cudaGetSymbolAddress((void**)&sl, g_sfc_lo);
    cudaGetSymbolAddress((void**)&qh, g_spj_hi); cudaGetSymbolAddress((void**)&ql, g_spj_lo);

    const int n4_x  = T_TOK * D_DIM / 4;
    const int n4_w  = E_NUM * FF * D_DIM / 4;
    const int n4_s  = FF * D_DIM / 4;
    cvt_plane<<<(n4_x + 255) / 256, 256>>>((const float4*)x,     xh, xl, n4_x);
    cvt_plane<<<(n4_w + 255) / 256, 256>>>((const float4*)wfc,   fh, fl, n4_w);
    cvt_plane<<<(n4_w + 255) / 256, 256>>>((const float4*)wproj, ph, pl, n4_w);
    cvt_plane<<<(n4_s + 255) / 256, 256>>>((const float4*)sfc,   sh, sl, n4_s);
    cvt_plane<<<(n4_s + 255) / 256, 256>>>((const float4*)sproj, qh, ql, n4_s);

    init_kernel<<<(NSLOT + 255) / 256, 256>>>();
    router_kernel<<<T_TOK / 8, 256>>>(x, rw);
    offsets_kernel<<<1, 32>>>();
    assign_kernel<<<T_TOK / 256, 256>>>();
    zero_out_kernel<<<(T_TOK * D_DIM / 4 + 255) / 256, 256>>>((float4*)out);

    // GEMM1: h = relu(gathered_x @ Wfc^T)^2
    moe_mma<D_DIM, true ><<<dim3(FF / BN,    NSLOT / BM), 256, SMEM_TOTAL>>>(nullptr);
    // GEMM2: out += w * (h @ Wproj^T)
    moe_mma<FF,    false><<<dim3(D_DIM / BN, NSLOT / BM), 256, SMEM_TOTAL>>>(out);
}

// round 6
// speedup vs baseline: 3.9264x; 1.4367x over previous
#include <cuda_runtime.h>
#include <cuda_fp16.h>
#include <cstdint>
#include <math.h>

// ---------------- problem constants ----------------
#define T_TOK   8192
#define D_DIM   1024
#define E_NUM   8
#define FF      4096
#define SHARED_BASE 17408
#define NSLOT       25600            // 200 * 128

#define BM  128
#define BN  128
#define BK  64                        // halves per K-chunk (128 B per row)
#define TILE_B 16384                  // 128 rows * 128 B
#define A_HI 0
#define A_LO 16384
#define B_HI 32768
#define BUF_B 49152                   // 3 tiles per stage
#define STAGES 4
#define SMEM_TOTAL (STAGES * BUF_B)   // 196608

// ---------------- scratch (static __device__, no allocation) ----------------
static __device__ int   g_slot_token [NSLOT];
static __device__ float g_slot_weight[NSLOT];
static __device__ int   g_slot_expert[NSLOT];
static __device__ int   g_counts[E_NUM];
static __device__ int   g_fill  [E_NUM];
static __device__ int   g_aoff  [E_NUM];
static __device__ int   g_tok_idx[T_TOK * 2];
static __device__ float g_tok_w  [T_TOK * 2];

// fp16 planes: activations get hi+lo (full precision A), weights hi only
static __device__ __half g_x_hi  [(size_t)T_TOK * D_DIM];
static __device__ __half g_x_lo  [(size_t)T_TOK * D_DIM];
static __device__ __half g_wfc_hi[(size_t)E_NUM * FF * D_DIM];
static __device__ __half g_wpj_hi[(size_t)E_NUM * D_DIM * FF];
static __device__ __half g_sfc_hi[(size_t)FF * D_DIM];
static __device__ __half g_spj_hi[(size_t)D_DIM * FF];
static __device__ __half g_h_hi  [(size_t)NSLOT * FF];
static __device__ __half g_h_lo  [(size_t)NSLOT * FF];

// ---------------- helpers ----------------
__device__ __forceinline__ uint32_t smem_u32(const void* p) {
    uint32_t a;
    asm("{ .reg .u64 t; cvta.to.shared.u64 t, %1; cvt.u32.u64 %0, t; }" : "=r"(a) : "l"(p));
    return a;
}
__device__ __forceinline__ void ldm_x4(uint32_t addr, uint32_t r[4]) {
    asm volatile("ldmatrix.sync.aligned.m8n8.x4.shared.b16 {%0,%1,%2,%3}, [%4];"
                 : "=r"(r[0]), "=r"(r[1]), "=r"(r[2]), "=r"(r[3]) : "r"(addr));
}
__device__ __forceinline__ void mma16816(float d[4], const uint32_t a[4], const uint32_t b[2]) {
    asm volatile("mma.sync.aligned.m16n8k16.row.col.f32.f16.f16.f32 "
                 "{%0,%1,%2,%3}, {%4,%5,%6,%7}, {%8,%9}, {%0,%1,%2,%3};"
                 : "+f"(d[0]), "+f"(d[1]), "+f"(d[2]), "+f"(d[3])
                 : "r"(a[0]), "r"(a[1]), "r"(a[2]), "r"(a[3]), "r"(b[0]), "r"(b[1]));
}
__device__ __forceinline__ void cp16(uint32_t saddr, const void* gaddr, uint32_t src_sz) {
    asm volatile("cp.async.cg.shared.global [%0], [%1], 16, %2;"
                 :: "r"(saddr), "l"(gaddr), "r"(src_sz) : "memory");
}
__device__ __forceinline__ void cp_commit() {
    asm volatile("cp.async.commit_group;" ::: "memory");
}
template <int N>
__device__ __forceinline__ void cp_wait() {
    asm volatile("cp.async.wait_group %0;" :: "n"(N) : "memory");
}

// ---------------- pre-convert kernels ----------------
static __global__ void cvt_plane(const float4* __restrict__ src,
                                 __half* __restrict__ hi, __half* __restrict__ lo,
                                 int n4) {
    int i = blockIdx.x * blockDim.x + threadIdx.x;
    if (i >= n4) return;
    float4 v = src[i];
    __half2 h0 = __floats2half2_rn(v.x, v.y);
    __half2 h1 = __floats2half2_rn(v.z, v.w);
    float2 f0 = __half22float2(h0);
    float2 f1 = __half22float2(h1);
    __half2 l0 = __floats2half2_rn(v.x - f0.x, v.y - f0.y);
    __half2 l1 = __floats2half2_rn(v.z - f1.x, v.w - f1.y);
    *(uint2*)(hi + 4 * (size_t)i) =
        make_uint2(*reinterpret_cast<uint32_t*>(&h0), *reinterpret_cast<uint32_t*>(&h1));
    *(uint2*)(lo + 4 * (size_t)i) =
        make_uint2(*reinterpret_cast<uint32_t*>(&l0), *reinterpret_cast<uint32_t*>(&l1));
}
static __global__ void cvt_hi(const float4* __restrict__ src,
                              __half* __restrict__ hi, int n4) {
    int i = blockIdx.x * blockDim.x + threadIdx.x;
    if (i >= n4) return;
    float4 v = src[i];
    __half2 h0 = __floats2half2_rn(v.x, v.y);
    __half2 h1 = __floats2half2_rn(v.z, v.w);
    *(uint2*)(hi + 4 * (size_t)i) =
        make_uint2(*reinterpret_cast<uint32_t*>(&h0), *reinterpret_cast<uint32_t*>(&h1));
}

// ---------------- routing kernels ----------------
static __global__ void init_kernel() {
    int s = blockIdx.x * blockDim.x + threadIdx.x;
    if (s < NSLOT) {
        if (s < SHARED_BASE) {
            g_slot_token[s] = -1; g_slot_weight[s] = 0.f; g_slot_expert[s] = 0;
        } else {
            g_slot_token[s] = s - SHARED_BASE; g_slot_weight[s] = 1.f; g_slot_expert[s] = E_NUM;
        }
    }
    if (s < E_NUM) { g_counts[s] = 0; g_fill[s] = 0; }
}

static __global__ void router_kernel(const float* __restrict__ x,
                                     const float* __restrict__ rw) {
    int gwarp = (blockIdx.x * blockDim.x + threadIdx.x) >> 5;
    int lane  = threadIdx.x & 31;
    if (gwarp >= T_TOK) return;
    const float* xr = x + (size_t)gwarp * D_DIM;
    float acc[E_NUM];
#pragma unroll
    for (int e = 0; e < E_NUM; e++) acc[e] = 0.f;
    for (int d = lane; d < D_DIM; d += 32) {
        float xv = xr[d];
#pragma unroll
        for (int e = 0; e < E_NUM; e++) acc[e] += xv * rw[e * D_DIM + d];
    }
#pragma unroll
    for (int e = 0; e < E_NUM; e++)
#pragma unroll
        for (int o = 16; o > 0; o >>= 1)
            acc[e] += __shfl_xor_sync(0xFFFFFFFFu, acc[e], o);
    if (lane == 0) {
        int i1 = 0; float l1 = acc[0];
#pragma unroll
        for (int e = 1; e < E_NUM; e++) if (acc[e] > l1) { l1 = acc[e]; i1 = e; }
        int i2 = -1; float l2 = -INFINITY;
#pragma unroll
        for (int e = 0; e < E_NUM; e++)
            if (e != i1 && acc[e] > l2) { l2 = acc[e]; i2 = e; }
        float w1 = 1.f / (1.f + expf(l2 - l1));
        float w2 = 1.f - w1;
        g_tok_idx[gwarp * 2 + 0] = i1;  g_tok_idx[gwarp * 2 + 1] = i2;
        g_tok_w  [gwarp * 2 + 0] = w1;  g_tok_w  [gwarp * 2 + 1] = w2;
        atomicAdd(&g_counts[i1], 1);    atomicAdd(&g_counts[i2], 1);
    }
}

static __global__ void offsets_kernel() {
    if (blockIdx.x == 0 && threadIdx.x == 0) {
        int off = 0;
#pragma unroll
        for (int e = 0; e < E_NUM; e++) {
            g_aoff[e] = off;
            off = (off + g_counts[e] + 127) & ~127;
        }
    }
}

static __global__ void assign_kernel() {
    int t = blockIdx.x * blockDim.x + threadIdx.x;
    if (t >= T_TOK) return;
#pragma unroll
    for (int k = 0; k < 2; k++) {
        int   e = g_tok_idx[t * 2 + k];
        float w = g_tok_w  [t * 2 + k];
        int pos = atomicAdd(&g_fill[e], 1);
        int s   = g_aoff[e] + pos;
        g_slot_token[s] = t; g_slot_weight[s] = w; g_slot_expert[s] = e;
    }
}

static __global__ void zero_out_kernel(float4* __restrict__ out) {
    int i = blockIdx.x * blockDim.x + threadIdx.x;
    if (i < (T_TOK * D_DIM) / 4) out[i] = make_float4(0.f, 0.f, 0.f, 0.f);
}

// ---------------- fp16x2 mma.sync ragged GEMM, cp.async 4-stage ----------------
// D = (a_hi + a_lo) @ b_hi^T  == full-precision activations x fp16 weights
// IS_FC:  h = relu(gathered_x @ Wfc^T)^2 -> g_h_hi/lo
// !IS_FC: out[tok] += w * (g_h @ Wproj^T)
template <int KDIM, bool IS_FC>
static __global__ void __launch_bounds__(256, 1)
moe_mma(float* __restrict__ outp)
{
    extern __shared__ __align__(16) char smem[];
    const uint32_t sb = smem_u32(smem);

    const int tid  = threadIdx.x;
    const int wid  = tid >> 5, lane = tid & 31;
    const int wm   = wid >> 1, wn = wid & 1;       // 4 x 2 warp grid
    const int m0   = blockIdx.y * BM, n0 = blockIdx.x * BN;
    const int expert = g_slot_expert[m0];

    // select operand planes
    const __half *Ah, *Al, *Bh;
    if (IS_FC) {
        Ah = g_x_hi; Al = g_x_lo;
        Bh = (expert < E_NUM) ? g_wfc_hi + (size_t)expert * FF * D_DIM : g_sfc_hi;
    } else {
        Ah = g_h_hi; Al = g_h_lo;
        Bh = (expert < E_NUM) ? g_wpj_hi + (size_t)expert * D_DIM * FF : g_spj_hi;
    }

    // ---- loader mapping: rows lr+32p (p=0..3), 16B col g ----
    const int lr = tid >> 3;
    const int g  = tid & 7;
    const __half* aHp[4]; const __half* aLp[4]; const __half* bHp[4];
    uint32_t asz[4];                    // 16 = copy, 0 = zero-fill (padding rows)
    uint32_t soff[4];
#pragma unroll
    for (int p = 0; p < 4; p++) {
        int row  = lr + 32 * p;
        int slot = m0 + row;
        size_t abase = 0;
        uint32_t sz = 16;
        if (IS_FC) {
            int tok = g_slot_token[slot];
            if (tok >= 0) abase = (size_t)tok * KDIM; else sz = 0;
        } else {
            abase = (size_t)slot * KDIM;
        }
        asz[p] = sz;
        aHp[p] = Ah + abase;
        aLp[p] = Al + abase;
        bHp[p] = Bh + (size_t)(n0 + row) * KDIM;
        soff[p] = (uint32_t)row * 128 + (((uint32_t)g * 16) ^ (((uint32_t)row & 7) * 16));
    }

    // ---- ldmatrix lane address parts (within tile, swizzled) ----
    uint32_t preA[2], xvA[2], preB[4], xvB[4];
    const uint32_t cA = ((uint32_t)lane >> 4) * 16;
    const uint32_t cB = (((uint32_t)lane >> 3) & 1) * 16;
#pragma unroll
    for (int mt = 0; mt < 2; mt++) {
        uint32_t rowA = wm * 32 + mt * 16 + (lane & 15);
        preA[mt] = rowA * 128;
        xvA[mt]  = (rowA & 7) * 16;
    }
#pragma unroll
    for (int p = 0; p < 4; p++) {
        uint32_t rowB = wn * 64 + p * 16 + (lane & 7) + (((uint32_t)lane >> 4) << 3);
        preB[p] = rowB * 128;
        xvB[p]  = (rowB & 7) * 16;
    }

    float acc[2][8][4];
#pragma unroll
    for (int mt = 0; mt < 2; mt++)
#pragma unroll
        for (int nt = 0; nt < 8; nt++)
#pragma unroll
            for (int j = 0; j < 4; j++) acc[mt][nt][j] = 0.f;

    auto issue_stage = [&](int kc) {
        const uint32_t bb = sb + (uint32_t)(kc % STAGES) * BUF_B;
        const int kb = kc * BK + g * 8;
#pragma unroll
        for (int p = 0; p < 4; p++) {
            cp16(bb + A_HI + soff[p], aHp[p] + kb, asz[p]);
            cp16(bb + A_LO + soff[p], aLp[p] + kb, asz[p]);
            cp16(bb + B_HI + soff[p], bHp[p] + kb, 16u);
        }
    };

    auto mma_chunk = [&](uint32_t bb) {
#pragma unroll
        for (int kk = 0; kk < 4; kk++) {
            const uint32_t kb = (uint32_t)kk * 32;
            uint32_t ah[2][4], al[2][4], bh[8][2];
#pragma unroll
            for (int mt = 0; mt < 2; mt++) {
                ldm_x4(bb + A_HI + preA[mt] + ((cA + kb) ^ xvA[mt]), ah[mt]);
                ldm_x4(bb + A_LO + preA[mt] + ((cA + kb) ^ xvA[mt]), al[mt]);
            }
#pragma unroll
            for (int p = 0; p < 4; p++) {
                uint32_t t[4];
                ldm_x4(bb + B_HI + preB[p] + ((cB + kb) ^ xvB[p]), t);
                bh[2*p][0] = t[0]; bh[2*p][1] = t[1];
                bh[2*p+1][0] = t[2]; bh[2*p+1][1] = t[3];
            }
#pragma unroll
            for (int mt = 0; mt < 2; mt++)
#pragma unroll
                for (int nt = 0; nt < 8; nt++) {
                    mma16816(acc[mt][nt], ah[mt], bh[nt]);
                    mma16816(acc[mt][nt], al[mt], bh[nt]);
                }
        }
    };

    const int NK = KDIM / BK;
    // prologue: fill STAGES-1 stages
#pragma unroll
    for (int s = 0; s < STAGES - 1; s++) {
        issue_stage(s);
        cp_commit();
    }
    for (int kc = 0; kc < NK; kc++) {
        cp_wait<STAGES - 2>();          // stage kc arrived
        __syncthreads();                // all threads see it; prev MMA done
        if (kc + STAGES - 1 < NK) issue_stage(kc + STAGES - 1);
        cp_commit();                    // keep group count aligned
        mma_chunk(sb + (uint32_t)(kc % STAGES) * BUF_B);
    }

    // ---------------- epilogue ----------------
    const int qn = 2 * (lane & 3);
#pragma unroll
    for (int mt = 0; mt < 2; mt++) {
#pragma unroll
        for (int half = 0; half < 2; half++) {
            const int row  = wm * 32 + mt * 16 + (lane >> 2) + 8 * half;
            const int slot = m0 + row;
            if (IS_FC) {
                const size_t base = (size_t)slot * FF + n0 + wn * 64 + qn;
#pragma unroll
                for (int nt = 0; nt < 8; nt++) {
                    float v0 = fmaxf(acc[mt][nt][2 * half + 0], 0.f); v0 *= v0;
                    float v1 = fmaxf(acc[mt][nt][2 * half + 1], 0.f); v1 *= v1;
                    __half2 h = __floats2half2_rn(v0, v1);
                    float2 f = __half22float2(h);
                    __half2 l = __floats2half2_rn(v0 - f.x, v1 - f.y);
                    *(uint32_t*)&g_h_hi[base + nt * 8] = *reinterpret_cast<uint32_t*>(&h);
                    *(uint32_t*)&g_h_lo[base + nt * 8] = *reinterpret_cast<uint32_t*>(&l);
                }
            } else {
                const int   tok = g_slot_token[slot];
                const float w   = g_slot_weight[slot];
                if (tok >= 0 && w != 0.f) {
                    float* orow = outp + (size_t)tok * D_DIM + n0 + wn * 64 + qn;
#pragma unroll
                    for (int nt = 0; nt < 8; nt++) {
                        atomicAdd(orow + nt * 8 + 0, w * acc[mt][nt][2 * half + 0]);
                        atomicAdd(orow + nt * 8 + 1, w * acc[mt][nt][2 * half + 1]);
                    }
                }
            }
        }
    }
}

// ---------------- launch ----------------
extern "C" void kernel_launch(void* const* d_in, const int* in_sizes, int n_in,
                              void* d_out, int out_size) {
    const float* x     = (const float*)d_in[0];   // [4,2048,1024]
    const float* rw    = (const float*)d_in[1];   // [8,1024]
    const float* wfc   = (const float*)d_in[2];   // [8,4096,1024]
    const float* wproj = (const float*)d_in[3];   // [8,1024,4096]
    const float* sfc   = (const float*)d_in[4];   // [4096,1024]
    const float* sproj = (const float*)d_in[5];   // [1024,4096]
    float* out = (float*)d_out;                   // [4,2048,1024] fp32

    cudaFuncSetAttribute(moe_mma<D_DIM, true>,
                         cudaFuncAttributeMaxDynamicSharedMemorySize, SMEM_TOTAL);
    cudaFuncSetAttribute(moe_mma<FF, false>,
                         cudaFuncAttributeMaxDynamicSharedMemorySize, SMEM_TOTAL);

    __half *xh, *xl, *fh, *ph, *sh, *qh;
    cudaGetSymbolAddress((void**)&xh, g_x_hi);   cudaGetSymbolAddress((void**)&xl, g_x_lo);
    cudaGetSymbolAddress((void**)&fh, g_wfc_hi);
    cudaGetSymbolAddress((void**)&ph, g_wpj_hi);
    cudaGetSymbolAddress((void**)&sh, g_sfc_hi);
    cudaGetSymbolAddress((void**)&qh, g_spj_hi);

    const int n4_x  = T_TOK * D_DIM / 4;
    const int n4_w  = E_NUM * FF * D_DIM / 4;
    const int n4_s  = FF * D_DIM / 4;
    cvt_plane<<<(n4_x + 255) / 256, 256>>>((const float4*)x, xh, xl, n4_x);
    cvt_hi   <<<(n4_w + 255) / 256, 256>>>((const float4*)wfc,   fh, n4_w);
    cvt_hi   <<<(n4_w + 255) / 256, 256>>>((const float4*)wproj, ph, n4_w);
    cvt_hi   <<<(n4_s + 255) / 256, 256>>>((const float4*)sfc,   sh, n4_s);
    cvt_hi   <<<(n4_s + 255) / 256, 256>>>((const float4*)sproj, qh, n4_s);

    init_kernel<<<(NSLOT + 255) / 256, 256>>>();
    router_kernel<<<T_TOK / 8, 256>>>(x, rw);
    offsets_kernel<<<1, 32>>>();
    assign_kernel<<<T_TOK / 256, 256>>>();
    zero_out_kernel<<<(T_TOK * D_DIM / 4 + 255) / 256, 256>>>((float4*)out);

    // GEMM1: h = relu(gathered_x @ Wfc^T)^2
    moe_mma<D_DIM, true ><<<dim3(FF / BN,    NSLOT / BM), 256, SMEM_TOTAL>>>(nullptr);
    // GEMM2: out += w * (h @ Wproj^T)
    moe_mma<FF,    false><<<dim3(D_DIM / BN, NSLOT / BM), 256, SMEM_TOTAL>>>(out);
}

// round 7
// speedup vs baseline: 4.7949x; 1.2212x over previous
#include <cuda_runtime.h>
#include <cuda_fp16.h>
#include <cstdint>
#include <math.h>

// ---------------- problem constants ----------------
#define T_TOK   8192
#define D_DIM   1024
#define E_NUM   8
#define FF      4096
#define SHARED_BASE 17408
#define NSLOT       25600            // 200 * 128

#define BM  128
#define BN  128
#define BK  64                        // halves per K-chunk (128 B per row)
#define TILE_B 16384                  // 128 rows * 128 B
#define STAGES 4

// ---------------- scratch (static __device__, no allocation) ----------------
static __device__ int   g_slot_token [NSLOT];
static __device__ float g_slot_weight[NSLOT];
static __device__ int   g_slot_expert[NSLOT];
static __device__ int   g_counts[E_NUM];
static __device__ int   g_fill  [E_NUM];
static __device__ int   g_aoff  [E_NUM];
static __device__ int   g_tok_idx[T_TOK * 2];
static __device__ float g_tok_w  [T_TOK * 2];

// fp16 planes: x gets hi+lo (full precision), weights hi only, h single plane
static __device__ __half g_x_hi  [(size_t)T_TOK * D_DIM];
static __device__ __half g_x_lo  [(size_t)T_TOK * D_DIM];
static __device__ __half g_wfc_hi[(size_t)E_NUM * FF * D_DIM];
static __device__ __half g_wpj_hi[(size_t)E_NUM * D_DIM * FF];
static __device__ __half g_sfc_hi[(size_t)FF * D_DIM];
static __device__ __half g_spj_hi[(size_t)D_DIM * FF];
static __device__ __half g_h     [(size_t)NSLOT * FF];

// ---------------- helpers ----------------
__device__ __forceinline__ uint32_t smem_u32(const void* p) {
    uint32_t a;
    asm("{ .reg .u64 t; cvta.to.shared.u64 t, %1; cvt.u32.u64 %0, t; }" : "=r"(a) : "l"(p));
    return a;
}
__device__ __forceinline__ void ldm_x4(uint32_t addr, uint32_t r[4]) {
    asm volatile("ldmatrix.sync.aligned.m8n8.x4.shared.b16 {%0,%1,%2,%3}, [%4];"
                 : "=r"(r[0]), "=r"(r[1]), "=r"(r[2]), "=r"(r[3]) : "r"(addr));
}
__device__ __forceinline__ void mma16816(float d[4], const uint32_t a[4], const uint32_t b[2]) {
    asm volatile("mma.sync.aligned.m16n8k16.row.col.f32.f16.f16.f32 "
                 "{%0,%1,%2,%3}, {%4,%5,%6,%7}, {%8,%9}, {%0,%1,%2,%3};"
                 : "+f"(d[0]), "+f"(d[1]), "+f"(d[2]), "+f"(d[3])
                 : "r"(a[0]), "r"(a[1]), "r"(a[2]), "r"(a[3]), "r"(b[0]), "r"(b[1]));
}
__device__ __forceinline__ void cp16(uint32_t saddr, const void* gaddr, uint32_t src_sz) {
    asm volatile("cp.async.cg.shared.global [%0], [%1], 16, %2;"
                 :: "r"(saddr), "l"(gaddr), "r"(src_sz) : "memory");
}
__device__ __forceinline__ void cp_commit() {
    asm volatile("cp.async.commit_group;" ::: "memory");
}
template <int N>
__device__ __forceinline__ void cp_wait() {
    asm volatile("cp.async.wait_group %0;" :: "n"(N) : "memory");
}

// ---------------- pre-convert kernels ----------------
static __global__ void cvt_plane(const float4* __restrict__ src,
                                 __half* __restrict__ hi, __half* __restrict__ lo,
                                 int n4) {
    int i = blockIdx.x * blockDim.x + threadIdx.x;
    if (i >= n4) return;
    float4 v = src[i];
    __half2 h0 = __floats2half2_rn(v.x, v.y);
    __half2 h1 = __floats2half2_rn(v.z, v.w);
    float2 f0 = __half22float2(h0);
    float2 f1 = __half22float2(h1);
    __half2 l0 = __floats2half2_rn(v.x - f0.x, v.y - f0.y);
    __half2 l1 = __floats2half2_rn(v.z - f1.x, v.w - f1.y);
    *(uint2*)(hi + 4 * (size_t)i) =
        make_uint2(*reinterpret_cast<uint32_t*>(&h0), *reinterpret_cast<uint32_t*>(&h1));
    *(uint2*)(lo + 4 * (size_t)i) =
        make_uint2(*reinterpret_cast<uint32_t*>(&l0), *reinterpret_cast<uint32_t*>(&l1));
}
static __global__ void cvt_hi(const float4* __restrict__ src,
                              __half* __restrict__ hi, int n4) {
    int i = blockIdx.x * blockDim.x + threadIdx.x;
    if (i >= n4) return;
    float4 v = src[i];
    __half2 h0 = __floats2half2_rn(v.x, v.y);
    __half2 h1 = __floats2half2_rn(v.z, v.w);
    *(uint2*)(hi + 4 * (size_t)i) =
        make_uint2(*reinterpret_cast<uint32_t*>(&h0), *reinterpret_cast<uint32_t*>(&h1));
}

// ---------------- routing kernels ----------------
static __global__ void init_kernel() {
    int s = blockIdx.x * blockDim.x + threadIdx.x;
    if (s < NSLOT) {
        if (s < SHARED_BASE) {
            g_slot_token[s] = -1; g_slot_weight[s] = 0.f; g_slot_expert[s] = 0;
        } else {
            g_slot_token[s] = s - SHARED_BASE; g_slot_weight[s] = 1.f; g_slot_expert[s] = E_NUM;
        }
    }
    if (s < E_NUM) { g_counts[s] = 0; g_fill[s] = 0; }
}

static __global__ void router_kernel(const float* __restrict__ x,
                                     const float* __restrict__ rw) {
    int gwarp = (blockIdx.x * blockDim.x + threadIdx.x) >> 5;
    int lane  = threadIdx.x & 31;
    if (gwarp >= T_TOK) return;
    const float* xr = x + (size_t)gwarp * D_DIM;
    float acc[E_NUM];
#pragma unroll
    for (int e = 0; e < E_NUM; e++) acc[e] = 0.f;
    for (int d = lane; d < D_DIM; d += 32) {
        float xv = xr[d];
#pragma unroll
        for (int e = 0; e < E_NUM; e++) acc[e] += xv * rw[e * D_DIM + d];
    }
#pragma unroll
    for (int e = 0; e < E_NUM; e++)
#pragma unroll
        for (int o = 16; o > 0; o >>= 1)
            acc[e] += __shfl_xor_sync(0xFFFFFFFFu, acc[e], o);
    if (lane == 0) {
        int i1 = 0; float l1 = acc[0];
#pragma unroll
        for (int e = 1; e < E_NUM; e++) if (acc[e] > l1) { l1 = acc[e]; i1 = e; }
        int i2 = -1; float l2 = -INFINITY;
#pragma unroll
        for (int e = 0; e < E_NUM; e++)
            if (e != i1 && acc[e] > l2) { l2 = acc[e]; i2 = e; }
        float w1 = 1.f / (1.f + expf(l2 - l1));
        float w2 = 1.f - w1;
        g_tok_idx[gwarp * 2 + 0] = i1;  g_tok_idx[gwarp * 2 + 1] = i2;
        g_tok_w  [gwarp * 2 + 0] = w1;  g_tok_w  [gwarp * 2 + 1] = w2;
        atomicAdd(&g_counts[i1], 1);    atomicAdd(&g_counts[i2], 1);
    }
}

static __global__ void offsets_kernel() {
    if (blockIdx.x == 0 && threadIdx.x == 0) {
        int off = 0;
#pragma unroll
        for (int e = 0; e < E_NUM; e++) {
            g_aoff[e] = off;
            off = (off + g_counts[e] + 127) & ~127;
        }
    }
}

static __global__ void assign_kernel() {
    int t = blockIdx.x * blockDim.x + threadIdx.x;
    if (t >= T_TOK) return;
#pragma unroll
    for (int k = 0; k < 2; k++) {
        int   e = g_tok_idx[t * 2 + k];
        float w = g_tok_w  [t * 2 + k];
        int pos = atomicAdd(&g_fill[e], 1);
        int s   = g_aoff[e] + pos;
        g_slot_token[s] = t; g_slot_weight[s] = w; g_slot_expert[s] = e;
    }
}

static __global__ void zero_out_kernel(float4* __restrict__ out) {
    int i = blockIdx.x * blockDim.x + threadIdx.x;
    if (i < (T_TOK * D_DIM) / 4) out[i] = make_float4(0.f, 0.f, 0.f, 0.f);
}

// ---------------- mma.sync ragged GEMM, cp.async multi-stage ----------------
// IS_FC (2 A-planes): h = relu((x_hi + x_lo) @ Wfc_hi^T)^2 -> g_h (fp16)
// else (1 A-plane):   out[tok] += w * (g_h @ Wproj_hi^T)
template <int KDIM, bool IS_FC>
static __global__ void __launch_bounds__(256, 1)
moe_mma(float* __restrict__ outp)
{
    constexpr int APL   = IS_FC ? 2 : 1;              // A planes
    constexpr uint32_t A_HI  = 0;
    constexpr uint32_t A_LO  = TILE_B;                // only used when APL==2
    constexpr uint32_t B_HI  = APL * TILE_B;
    constexpr uint32_t BUF_B = (APL + 1) * TILE_B;    // 49152 or 32768

    extern __shared__ __align__(16) char smem[];
    const uint32_t sb = smem_u32(smem);

    const int tid  = threadIdx.x;
    const int wid  = tid >> 5, lane = tid & 31;
    const int wm   = wid >> 1, wn = wid & 1;       // 4 x 2 warp grid
    const int m0   = blockIdx.y * BM, n0 = blockIdx.x * BN;
    const int expert = g_slot_expert[m0];

    // select operand planes
    const __half *Ah, *Al, *Bh;
    if (IS_FC) {
        Ah = g_x_hi; Al = g_x_lo;
        Bh = (expert < E_NUM) ? g_wfc_hi + (size_t)expert * FF * D_DIM : g_sfc_hi;
    } else {
        Ah = g_h; Al = nullptr;
        Bh = (expert < E_NUM) ? g_wpj_hi + (size_t)expert * D_DIM * FF : g_spj_hi;
    }

    // ---- loader mapping: rows lr+32p (p=0..3), 16B col g ----
    const int lr = tid >> 3;
    const int g  = tid & 7;
    const __half* aHp[4]; const __half* aLp[4]; const __half* bHp[4];
    uint32_t asz[4];                    // 16 = copy, 0 = zero-fill (padding rows)
    uint32_t soff[4];
#pragma unroll
    for (int p = 0; p < 4; p++) {
        int row  = lr + 32 * p;
        int slot = m0 + row;
        size_t abase = 0;
        uint32_t sz = 16;
        if (IS_FC) {
            int tok = g_slot_token[slot];
            if (tok >= 0) abase = (size_t)tok * KDIM; else sz = 0;
        } else {
            abase = (size_t)slot * KDIM;
        }
        asz[p] = sz;
        aHp[p] = Ah + abase;
        aLp[p] = IS_FC ? Al + abase : nullptr;
        bHp[p] = Bh + (size_t)(n0 + row) * KDIM;
        soff[p] = (uint32_t)row * 128 + (((uint32_t)g * 16) ^ (((uint32_t)row & 7) * 16));
    }

    // ---- ldmatrix lane address parts (within tile, swizzled) ----
    uint32_t preA[2], xvA[2], preB[4], xvB[4];
    const uint32_t cA = ((uint32_t)lane >> 4) * 16;
    const uint32_t cB = (((uint32_t)lane >> 3) & 1) * 16;
#pragma unroll
    for (int mt = 0; mt < 2; mt++) {
        uint32_t rowA = wm * 32 + mt * 16 + (lane & 15);
        preA[mt] = rowA * 128;
        xvA[mt]  = (rowA & 7) * 16;
    }
#pragma unroll
    for (int p = 0; p < 4; p++) {
        uint32_t rowB = wn * 64 + p * 16 + (lane & 7) + (((uint32_t)lane >> 4) << 3);
        preB[p] = rowB * 128;
        xvB[p]  = (rowB & 7) * 16;
    }

    float acc[2][8][4];
#pragma unroll
    for (int mt = 0; mt < 2; mt++)
#pragma unroll
        for (int nt = 0; nt < 8; nt++)
#pragma unroll
            for (int j = 0; j < 4; j++) acc[mt][nt][j] = 0.f;

    auto issue_stage = [&](int kc) {
        const uint32_t bb = sb + (uint32_t)(kc % STAGES) * BUF_B;
        const int kb = kc * BK + g * 8;
#pragma unroll
        for (int p = 0; p < 4; p++) {
            cp16(bb + A_HI + soff[p], aHp[p] + kb, asz[p]);
            if (IS_FC) cp16(bb + A_LO + soff[p], aLp[p] + kb, asz[p]);
            cp16(bb + B_HI + soff[p], bHp[p] + kb, 16u);
        }
    };

    auto mma_chunk = [&](uint32_t bb) {
#pragma unroll
        for (int kk = 0; kk < 4; kk++) {
            const uint32_t kb = (uint32_t)kk * 32;
            uint32_t ah[2][4], al[2][4], bh[8][2];
#pragma unroll
            for (int mt = 0; mt < 2; mt++) {
                ldm_x4(bb + A_HI + preA[mt] + ((cA + kb) ^ xvA[mt]), ah[mt]);
                if (IS_FC)
                    ldm_x4(bb + A_LO + preA[mt] + ((cA + kb) ^ xvA[mt]), al[mt]);
            }
#pragma unroll
            for (int p = 0; p < 4; p++) {
                uint32_t t[4];
                ldm_x4(bb + B_HI + preB[p] + ((cB + kb) ^ xvB[p]), t);
                bh[2*p][0] = t[0]; bh[2*p][1] = t[1];
                bh[2*p+1][0] = t[2]; bh[2*p+1][1] = t[3];
            }
#pragma unroll
            for (int mt = 0; mt < 2; mt++)
#pragma unroll
                for (int nt = 0; nt < 8; nt++) {
                    mma16816(acc[mt][nt], ah[mt], bh[nt]);
                    if (IS_FC) mma16816(acc[mt][nt], al[mt], bh[nt]);
                }
        }
    };

    const int NK = KDIM / BK;
#pragma unroll
    for (int s = 0; s < STAGES - 1; s++) {
        issue_stage(s);
        cp_commit();
    }
    for (int kc = 0; kc < NK; kc++) {
        cp_wait<STAGES - 2>();
        __syncthreads();
        if (kc + STAGES - 1 < NK) issue_stage(kc + STAGES - 1);
        cp_commit();
        mma_chunk(sb + (uint32_t)(kc % STAGES) * BUF_B);
    }

    // ---------------- epilogue ----------------
    const int qn = 2 * (lane & 3);
#pragma unroll
    for (int mt = 0; mt < 2; mt++) {
#pragma unroll
        for (int half = 0; half < 2; half++) {
            const int row  = wm * 32 + mt * 16 + (lane >> 2) + 8 * half;
            const int slot = m0 + row;
            if (IS_FC) {
                const size_t base = (size_t)slot * FF + n0 + wn * 64 + qn;
#pragma unroll
                for (int nt = 0; nt < 8; nt++) {
                    float v0 = fmaxf(acc[mt][nt][2 * half + 0], 0.f); v0 *= v0;
                    float v1 = fmaxf(acc[mt][nt][2 * half + 1], 0.f); v1 *= v1;
                    __half2 h = __floats2half2_rn(v0, v1);
                    *(uint32_t*)&g_h[base + nt * 8] = *reinterpret_cast<uint32_t*>(&h);
                }
            } else {
                const int   tok = g_slot_token[slot];
                const float w   = g_slot_weight[slot];
                if (tok >= 0 && w != 0.f) {
                    float* orow = outp + (size_t)tok * D_DIM + n0 + wn * 64 + qn;
#pragma unroll
                    for (int nt = 0; nt < 8; nt++) {
                        atomicAdd(orow + nt * 8 + 0, w * acc[mt][nt][2 * half + 0]);
                        atomicAdd(orow + nt * 8 + 1, w * acc[mt][nt][2 * half + 1]);
                    }
                }
            }
        }
    }
}

// ---------------- launch ----------------
extern "C" void kernel_launch(void* const* d_in, const int* in_sizes, int n_in,
                              void* d_out, int out_size) {
    const float* x     = (const float*)d_in[0];   // [4,2048,1024]
    const float* rw    = (const float*)d_in[1];   // [8,1024]
    const float* wfc   = (const float*)d_in[2];   // [8,4096,1024]
    const float* wproj = (const float*)d_in[3];   // [8,1024,4096]
    const float* sfc   = (const float*)d_in[4];   // [4096,1024]
    const float* sproj = (const float*)d_in[5];   // [1024,4096]
    float* out = (float*)d_out;                   // [4,2048,1024] fp32

    const int SMEM1 = STAGES * 3 * TILE_B;   // 196608
    const int SMEM2 = STAGES * 2 * TILE_B;   // 131072
    cudaFuncSetAttribute(moe_mma<D_DIM, true>,
                         cudaFuncAttributeMaxDynamicSharedMemorySize, SMEM1);
    cudaFuncSetAttribute(moe_mma<FF, false>,
                         cudaFuncAttributeMaxDynamicSharedMemorySize, SMEM2);

    __half *xh, *xl, *fh, *ph, *sh, *qh;
    cudaGetSymbolAddress((void**)&xh, g_x_hi);   cudaGetSymbolAddress((void**)&xl, g_x_lo);
    cudaGetSymbolAddress((void**)&fh, g_wfc_hi);
    cudaGetSymbolAddress((void**)&ph, g_wpj_hi);
    cudaGetSymbolAddress((void**)&sh, g_sfc_hi);
    cudaGetSymbolAddress((void**)&qh, g_spj_hi);

    const int n4_x  = T_TOK * D_DIM / 4;
    const int n4_w  = E_NUM * FF * D_DIM / 4;
    const int n4_s  = FF * D_DIM / 4;
    cvt_plane<<<(n4_x + 255) / 256, 256>>>((const float4*)x, xh, xl, n4_x);
    cvt_hi   <<<(n4_w + 255) / 256, 256>>>((const float4*)wfc,   fh, n4_w);
    cvt_hi   <<<(n4_w + 255) / 256, 256>>>((const float4*)wproj, ph, n4_w);
    cvt_hi   <<<(n4_s + 255) / 256, 256>>>((const float4*)sfc,   sh, n4_s);
    cvt_hi   <<<(n4_s + 255) / 256, 256>>>((const float4*)sproj, qh, n4_s);

    init_kernel<<<(NSLOT + 255) / 256, 256>>>();
    router_kernel<<<T_TOK / 8, 256>>>(x, rw);
    offsets_kernel<<<1, 32>>>();
    assign_kernel<<<T_TOK / 256, 256>>>();
    zero_out_kernel<<<(T_TOK * D_DIM / 4 + 255) / 256, 256>>>((float4*)out);

    // GEMM1: h = relu(gathered_x @ Wfc^T)^2   (2 A-planes)
    moe_mma<D_DIM, true ><<<dim3(FF / BN,    NSLOT / BM), 256, SMEM1>>>(nullptr);
    // GEMM2: out += w * (h @ Wproj^T)         (1 A-plane)
    moe_mma<FF,    false><<<dim3(D_DIM / BN, NSLOT / BM), 256, SMEM2>>>(out);
}

// round 8
// speedup vs baseline: 5.9603x; 1.2430x over previous
#include <cuda_runtime.h>
#include <cuda_fp16.h>
#include <cstdint>
#include <math.h>

// ---------------- problem constants ----------------
#define T_TOK   8192
#define D_DIM   1024
#define E_NUM   8
#define FF      4096
#define SHARED_BASE 17408
#define NSLOT       25600            // 200 * 128

#define BM  128
#define BN  128
#define BK  64                        // halves per K-chunk (128 B per row)
#define TILE_B 16384                  // 128 rows * 128 B
#define A_OFF 0
#define B_OFF TILE_B
#define BUF_B (2 * TILE_B)            // 32768
#define STAGES 5
#define SMEM_TOTAL (STAGES * BUF_B)   // 163840

// ---------------- scratch (static __device__, no allocation) ----------------
static __device__ int   g_slot_token [NSLOT];
static __device__ float g_slot_weight[NSLOT];
static __device__ int   g_slot_expert[NSLOT];
static __device__ int   g_counts[E_NUM];
static __device__ int   g_fill  [E_NUM];
static __device__ int   g_aoff  [E_NUM];
static __device__ int   g_tok_idx[T_TOK * 2];
static __device__ float g_tok_w  [T_TOK * 2];

// fp16 single planes everywhere
static __device__ __half g_x  [(size_t)T_TOK * D_DIM];
static __device__ __half g_wfc[(size_t)E_NUM * FF * D_DIM];
static __device__ __half g_wpj[(size_t)E_NUM * D_DIM * FF];
static __device__ __half g_sfc[(size_t)FF * D_DIM];
static __device__ __half g_spj[(size_t)D_DIM * FF];
static __device__ __half g_h  [(size_t)NSLOT * FF];

// ---------------- helpers ----------------
__device__ __forceinline__ uint32_t smem_u32(const void* p) {
    uint32_t a;
    asm("{ .reg .u64 t; cvta.to.shared.u64 t, %1; cvt.u32.u64 %0, t; }" : "=r"(a) : "l"(p));
    return a;
}
__device__ __forceinline__ void ldm_x4(uint32_t addr, uint32_t r[4]) {
    asm volatile("ldmatrix.sync.aligned.m8n8.x4.shared.b16 {%0,%1,%2,%3}, [%4];"
                 : "=r"(r[0]), "=r"(r[1]), "=r"(r[2]), "=r"(r[3]) : "r"(addr));
}
__device__ __forceinline__ void mma16816(float d[4], const uint32_t a[4], const uint32_t b[2]) {
    asm volatile("mma.sync.aligned.m16n8k16.row.col.f32.f16.f16.f32 "
                 "{%0,%1,%2,%3}, {%4,%5,%6,%7}, {%8,%9}, {%0,%1,%2,%3};"
                 : "+f"(d[0]), "+f"(d[1]), "+f"(d[2]), "+f"(d[3])
                 : "r"(a[0]), "r"(a[1]), "r"(a[2]), "r"(a[3]), "r"(b[0]), "r"(b[1]));
}
__device__ __forceinline__ void cp16(uint32_t saddr, const void* gaddr, uint32_t src_sz) {
    asm volatile("cp.async.cg.shared.global [%0], [%1], 16, %2;"
                 :: "r"(saddr), "l"(gaddr), "r"(src_sz) : "memory");
}
__device__ __forceinline__ void cp_commit() {
    asm volatile("cp.async.commit_group;" ::: "memory");
}
template <int N>
__device__ __forceinline__ void cp_wait() {
    asm volatile("cp.async.wait_group %0;" :: "n"(N) : "memory");
}

// ---------------- pre-convert: fp32 -> fp16, 2 float4 per thread ----------------
static __global__ void cvt_hi2(const float4* __restrict__ src,
                               __half* __restrict__ dst, int n4) {
    int i = (blockIdx.x * blockDim.x + threadIdx.x) * 2;
    if (i >= n4) return;
#pragma unroll
    for (int j = 0; j < 2; j++) {
        if (i + j >= n4) break;
        float4 v = src[i + j];
        __half2 h0 = __floats2half2_rn(v.x, v.y);
        __half2 h1 = __floats2half2_rn(v.z, v.w);
        *(uint2*)(dst + 4 * (size_t)(i + j)) =
            make_uint2(*reinterpret_cast<uint32_t*>(&h0), *reinterpret_cast<uint32_t*>(&h1));
    }
}

// ---------------- routing kernels ----------------
static __global__ void init_kernel() {
    int s = blockIdx.x * blockDim.x + threadIdx.x;
    if (s < NSLOT) {
        if (s < SHARED_BASE) {
            g_slot_token[s] = -1; g_slot_weight[s] = 0.f; g_slot_expert[s] = 0;
        } else {
            g_slot_token[s] = s - SHARED_BASE; g_slot_weight[s] = 1.f; g_slot_expert[s] = E_NUM;
        }
    }
    if (s < E_NUM) { g_counts[s] = 0; g_fill[s] = 0; }
}

static __global__ void router_kernel(const float* __restrict__ x,
                                     const float* __restrict__ rw) {
    int gwarp = (blockIdx.x * blockDim.x + threadIdx.x) >> 5;
    int lane  = threadIdx.x & 31;
    if (gwarp >= T_TOK) return;
    const float* xr = x + (size_t)gwarp * D_DIM;
    float acc[E_NUM];
#pragma unroll
    for (int e = 0; e < E_NUM; e++) acc[e] = 0.f;
    for (int d = lane; d < D_DIM; d += 32) {
        float xv = xr[d];
#pragma unroll
        for (int e = 0; e < E_NUM; e++) acc[e] += xv * rw[e * D_DIM + d];
    }
#pragma unroll
    for (int e = 0; e < E_NUM; e++)
#pragma unroll
        for (int o = 16; o > 0; o >>= 1)
            acc[e] += __shfl_xor_sync(0xFFFFFFFFu, acc[e], o);
    if (lane == 0) {
        int i1 = 0; float l1 = acc[0];
#pragma unroll
        for (int e = 1; e < E_NUM; e++) if (acc[e] > l1) { l1 = acc[e]; i1 = e; }
        int i2 = -1; float l2 = -INFINITY;
#pragma unroll
        for (int e = 0; e < E_NUM; e++)
            if (e != i1 && acc[e] > l2) { l2 = acc[e]; i2 = e; }
        float w1 = 1.f / (1.f + expf(l2 - l1));
        float w2 = 1.f - w1;
        g_tok_idx[gwarp * 2 + 0] = i1;  g_tok_idx[gwarp * 2 + 1] = i2;
        g_tok_w  [gwarp * 2 + 0] = w1;  g_tok_w  [gwarp * 2 + 1] = w2;
        atomicAdd(&g_counts[i1], 1);    atomicAdd(&g_counts[i2], 1);
    }
}

static __global__ void offsets_kernel() {
    if (blockIdx.x == 0 && threadIdx.x == 0) {
        int off = 0;
#pragma unroll
        for (int e = 0; e < E_NUM; e++) {
            g_aoff[e] = off;
            off = (off + g_counts[e] + 127) & ~127;
        }
    }
}

static __global__ void assign_kernel() {
    int t = blockIdx.x * blockDim.x + threadIdx.x;
    if (t >= T_TOK) return;
#pragma unroll
    for (int k = 0; k < 2; k++) {
        int   e = g_tok_idx[t * 2 + k];
        float w = g_tok_w  [t * 2 + k];
        int pos = atomicAdd(&g_fill[e], 1);
        int s   = g_aoff[e] + pos;
        g_slot_token[s] = t; g_slot_weight[s] = w; g_slot_expert[s] = e;
    }
}

static __global__ void zero_out_kernel(float4* __restrict__ out) {
    int i = blockIdx.x * blockDim.x + threadIdx.x;
    if (i < (T_TOK * D_DIM) / 4) out[i] = make_float4(0.f, 0.f, 0.f, 0.f);
}

// ---------------- fp16 mma.sync ragged GEMM, cp.async 5-stage ----------------
// IS_FC:  h = relu(gathered_x @ Wfc^T)^2 -> g_h (fp16)
// else:   out[tok] += w * (g_h @ Wproj^T)
template <int KDIM, bool IS_FC>
static __global__ void __launch_bounds__(256, 1)
moe_mma(float* __restrict__ outp)
{
    extern __shared__ __align__(16) char smem[];
    const uint32_t sb = smem_u32(smem);

    const int tid  = threadIdx.x;
    const int wid  = tid >> 5, lane = tid & 31;
    const int wm   = wid >> 1, wn = wid & 1;       // 4 x 2 warp grid
    const int m0   = blockIdx.y * BM, n0 = blockIdx.x * BN;
    const int expert = g_slot_expert[m0];

    const __half *A, *B;
    if (IS_FC) {
        A = g_x;
        B = (expert < E_NUM) ? g_wfc + (size_t)expert * FF * D_DIM : g_sfc;
    } else {
        A = g_h;
        B = (expert < E_NUM) ? g_wpj + (size_t)expert * D_DIM * FF : g_spj;
    }

    // ---- loader mapping: rows lr+32p (p=0..3), 16B col g ----
    const int lr = tid >> 3;
    const int g  = tid & 7;
    const __half* aP[4]; const __half* bP[4];
    uint32_t asz[4];                    // 16 = copy, 0 = zero-fill (padding rows)
    uint32_t soff[4];
#pragma unroll
    for (int p = 0; p < 4; p++) {
        int row  = lr + 32 * p;
        int slot = m0 + row;
        size_t abase = 0;
        uint32_t sz = 16;
        if (IS_FC) {
            int tok = g_slot_token[slot];
            if (tok >= 0) abase = (size_t)tok * KDIM; else sz = 0;
        } else {
            abase = (size_t)slot * KDIM;
        }
        asz[p] = sz;
        aP[p] = A + abase;
        bP[p] = B + (size_t)(n0 + row) * KDIM;
        soff[p] = (uint32_t)row * 128 + (((uint32_t)g * 16) ^ (((uint32_t)row & 7) * 16));
    }

    // ---- ldmatrix lane address parts (within tile, swizzled) ----
    uint32_t preA[2], xvA[2], preB[4], xvB[4];
    const uint32_t cA = ((uint32_t)lane >> 4) * 16;
    const uint32_t cB = (((uint32_t)lane >> 3) & 1) * 16;
#pragma unroll
    for (int mt = 0; mt < 2; mt++) {
        uint32_t rowA = wm * 32 + mt * 16 + (lane & 15);
        preA[mt] = rowA * 128;
        xvA[mt]  = (rowA & 7) * 16;
    }
#pragma unroll
    for (int p = 0; p < 4; p++) {
        uint32_t rowB = wn * 64 + p * 16 + (lane & 7) + (((uint32_t)lane >> 4) << 3);
        preB[p] = rowB * 128;
        xvB[p]  = (rowB & 7) * 16;
    }

    float acc[2][8][4];
#pragma unroll
    for (int mt = 0; mt < 2; mt++)
#pragma unroll
        for (int nt = 0; nt < 8; nt++)
#pragma unroll
            for (int j = 0; j < 4; j++) acc[mt][nt][j] = 0.f;

    auto issue_stage = [&](int kc) {
        const uint32_t bb = sb + (uint32_t)(kc % STAGES) * BUF_B;
        const int kb = kc * BK + g * 8;
#pragma unroll
        for (int p = 0; p < 4; p++) {
            cp16(bb + A_OFF + soff[p], aP[p] + kb, asz[p]);
            cp16(bb + B_OFF + soff[p], bP[p] + kb, 16u);
        }
    };

    auto mma_chunk = [&](uint32_t bb) {
#pragma unroll
        for (int kk = 0; kk < 4; kk++) {
            const uint32_t kb = (uint32_t)kk * 32;
            uint32_t ah[2][4], bh[8][2];
#pragma unroll
            for (int mt = 0; mt < 2; mt++)
                ldm_x4(bb + A_OFF + preA[mt] + ((cA + kb) ^ xvA[mt]), ah[mt]);
#pragma unroll
            for (int p = 0; p < 4; p++) {
                uint32_t t[4];
                ldm_x4(bb + B_OFF + preB[p] + ((cB + kb) ^ xvB[p]), t);
                bh[2*p][0] = t[0]; bh[2*p][1] = t[1];
                bh[2*p+1][0] = t[2]; bh[2*p+1][1] = t[3];
            }
#pragma unroll
            for (int mt = 0; mt < 2; mt++)
#pragma unroll
                for (int nt = 0; nt < 8; nt++)
                    mma16816(acc[mt][nt], ah[mt], bh[nt]);
        }
    };

    const int NK = KDIM / BK;
#pragma unroll
    for (int s = 0; s < STAGES - 1; s++) {
        issue_stage(s);
        cp_commit();
    }
    for (int kc = 0; kc < NK; kc++) {
        cp_wait<STAGES - 2>();
        __syncthreads();
        if (kc + STAGES - 1 < NK) issue_stage(kc + STAGES - 1);
        cp_commit();
        mma_chunk(sb + (uint32_t)(kc % STAGES) * BUF_B);
    }

    // ---------------- epilogue ----------------
    const int qn = 2 * (lane & 3);
#pragma unroll
    for (int mt = 0; mt < 2; mt++) {
#pragma unroll
        for (int half = 0; half < 2; half++) {
            const int row  = wm * 32 + mt * 16 + (lane >> 2) + 8 * half;
            const int slot = m0 + row;
            if (IS_FC) {
                const size_t base = (size_t)slot * FF + n0 + wn * 64 + qn;
#pragma unroll
                for (int nt = 0; nt < 8; nt++) {
                    float v0 = fmaxf(acc[mt][nt][2 * half + 0], 0.f); v0 *= v0;
                    float v1 = fmaxf(acc[mt][nt][2 * half + 1], 0.f); v1 *= v1;
                    __half2 h = __floats2half2_rn(v0, v1);
                    *(uint32_t*)&g_h[base + nt * 8] = *reinterpret_cast<uint32_t*>(&h);
                }
            } else {
                const int   tok = g_slot_token[slot];
                const float w   = g_slot_weight[slot];
                if (tok >= 0 && w != 0.f) {
                    float* orow = outp + (size_t)tok * D_DIM + n0 + wn * 64 + qn;
#pragma unroll
                    for (int nt = 0; nt < 8; nt++) {
                        atomicAdd(orow + nt * 8 + 0, w * acc[mt][nt][2 * half + 0]);
                        atomicAdd(orow + nt * 8 + 1, w * acc[mt][nt][2 * half + 1]);
                    }
                }
            }
        }
    }
}

// ---------------- launch ----------------
extern "C" void kernel_launch(void* const* d_in, const int* in_sizes, int n_in,
                              void* d_out, int out_size) {
    const float* x     = (const float*)d_in[0];   // [4,2048,1024]
    const float* rw    = (const float*)d_in[1];   // [8,1024]
    const float* wfc   = (const float*)d_in[2];   // [8,4096,1024]
    const float* wproj = (const float*)d_in[3];   // [8,1024,4096]
    const float* sfc   = (const float*)d_in[4];   // [4096,1024]
    const float* sproj = (const float*)d_in[5];   // [1024,4096]
    float* out = (float*)d_out;                   // [4,2048,1024] fp32

    cudaFuncSetAttribute(moe_mma<D_DIM, true>,
                         cudaFuncAttributeMaxDynamicSharedMemorySize, SMEM_TOTAL);
    cudaFuncSetAttribute(moe_mma<FF, false>,
                         cudaFuncAttributeMaxDynamicSharedMemorySize, SMEM_TOTAL);

    __half *xh, *fh, *ph, *sh, *qh;
    cudaGetSymbolAddress((void**)&xh, g_x);
    cudaGetSymbolAddress((void**)&fh, g_wfc);
    cudaGetSymbolAddress((void**)&ph, g_wpj);
    cudaGetSymbolAddress((void**)&sh, g_sfc);
    cudaGetSymbolAddress((void**)&qh, g_spj);

    const int n4_x  = T_TOK * D_DIM / 4;
    const int n4_w  = E_NUM * FF * D_DIM / 4;
    const int n4_s  = FF * D_DIM / 4;
    cvt_hi2<<<(n4_x / 2 + 255) / 256, 256>>>((const float4*)x,     xh, n4_x);
    cvt_hi2<<<(n4_w / 2 + 255) / 256, 256>>>((const float4*)wfc,   fh, n4_w);
    cvt_hi2<<<(n4_w / 2 + 255) / 256, 256>>>((const float4*)wproj, ph, n4_w);
    cvt_hi2<<<(n4_s / 2 + 255) / 256, 256>>>((const float4*)sfc,   sh, n4_s);
    cvt_hi2<<<(n4_s / 2 + 255) / 256, 256>>>((const float4*)sproj, qh, n4_s);

    init_kernel<<<(NSLOT + 255) / 256, 256>>>();
    router_kernel<<<T_TOK / 8, 256>>>(x, rw);
    offsets_kernel<<<1, 32>>>();
    assign_kernel<<<T_TOK / 256, 256>>>();
    zero_out_kernel<<<(T_TOK * D_DIM / 4 + 255) / 256, 256>>>((float4*)out);

    // GEMM1: h = relu(gathered_x @ Wfc^T)^2
    moe_mma<D_DIM, true ><<<dim3(FF / BN,    NSLOT / BM), 256, SMEM_TOTAL>>>(nullptr);
    // GEMM2: out += w * (h @ Wproj^T)
    moe_mma<FF,    false><<<dim3(D_DIM / BN, NSLOT / BM), 256, SMEM_TOTAL>>>(out);
}

// round 9
// speedup vs baseline: 6.8730x; 1.1531x over previous
#include <cuda_runtime.h>
#include <cuda_fp16.h>
#include <cstdint>
#include <math.h>

// ---------------- problem constants ----------------
#define T_TOK   8192
#define D_DIM   1024
#define E_NUM   8
#define FF      4096
#define SHARED_BASE 17408
#define NSLOT       25600            // 200 * 128

#define BM  128
#define BN  256
#define BK  64                        // halves per K-chunk (128 B per row)
#define TILE_A 16384                  // 128 rows * 128 B
#define TILE_BB 32768                 // 256 rows * 128 B
#define A_OFF 0
#define B_OFF TILE_A
#define BUF_B (TILE_A + TILE_BB)      // 49152
#define STAGES 4
#define SMEM_TOTAL (STAGES * BUF_B)   // 196608

// ---------------- scratch (static __device__, no allocation) ----------------
static __device__ int   g_slot_token [NSLOT];
static __device__ float g_slot_weight[NSLOT];
static __device__ int   g_slot_expert[NSLOT];
static __device__ int   g_counts[E_NUM];
static __device__ int   g_fill  [E_NUM];
static __device__ int   g_aoff  [E_NUM];
static __device__ int   g_tok_idx[T_TOK * 2];
static __device__ float g_tok_w  [T_TOK * 2];

// fp16 single planes everywhere
static __device__ __half g_x  [(size_t)T_TOK * D_DIM];
static __device__ __half g_wfc[(size_t)E_NUM * FF * D_DIM];
static __device__ __half g_wpj[(size_t)E_NUM * D_DIM * FF];
static __device__ __half g_sfc[(size_t)FF * D_DIM];
static __device__ __half g_spj[(size_t)D_DIM * FF];
static __device__ __half g_h  [(size_t)NSLOT * FF];

// ---------------- helpers ----------------
__device__ __forceinline__ uint32_t smem_u32(const void* p) {
    uint32_t a;
    asm("{ .reg .u64 t; cvta.to.shared.u64 t, %1; cvt.u32.u64 %0, t; }" : "=r"(a) : "l"(p));
    return a;
}
__device__ __forceinline__ void ldm_x4(uint32_t addr, uint32_t r[4]) {
    asm volatile("ldmatrix.sync.aligned.m8n8.x4.shared.b16 {%0,%1,%2,%3}, [%4];"
                 : "=r"(r[0]), "=r"(r[1]), "=r"(r[2]), "=r"(r[3]) : "r"(addr));
}
__device__ __forceinline__ void mma16816(float d[4], const uint32_t a[4], const uint32_t b[2]) {
    asm volatile("mma.sync.aligned.m16n8k16.row.col.f32.f16.f16.f32 "
                 "{%0,%1,%2,%3}, {%4,%5,%6,%7}, {%8,%9}, {%0,%1,%2,%3};"
                 : "+f"(d[0]), "+f"(d[1]), "+f"(d[2]), "+f"(d[3])
                 : "r"(a[0]), "r"(a[1]), "r"(a[2]), "r"(a[3]), "r"(b[0]), "r"(b[1]));
}
__device__ __forceinline__ void cp16(uint32_t saddr, const void* gaddr, uint32_t src_sz) {
    asm volatile("cp.async.cg.shared.global [%0], [%1], 16, %2;"
                 :: "r"(saddr), "l"(gaddr), "r"(src_sz) : "memory");
}
__device__ __forceinline__ void cp_commit() {
    asm volatile("cp.async.commit_group;" ::: "memory");
}
template <int N>
__device__ __forceinline__ void cp_wait() {
    asm volatile("cp.async.wait_group %0;" :: "n"(N) : "memory");
}

// ---------------- pre-convert: fp32 -> fp16, 2 float4 per thread ----------------
static __global__ void cvt_hi2(const float4* __restrict__ src,
                               __half* __restrict__ dst, int n4) {
    int i = (blockIdx.x * blockDim.x + threadIdx.x) * 2;
    if (i >= n4) return;
#pragma unroll
    for (int j = 0; j < 2; j++) {
        if (i + j >= n4) break;
        float4 v = src[i + j];
        __half2 h0 = __floats2half2_rn(v.x, v.y);
        __half2 h1 = __floats2half2_rn(v.z, v.w);
        *(uint2*)(dst + 4 * (size_t)(i + j)) =
            make_uint2(*reinterpret_cast<uint32_t*>(&h0), *reinterpret_cast<uint32_t*>(&h1));
    }
}

// ---------------- routing kernels ----------------
static __global__ void init_kernel() {
    int s = blockIdx.x * blockDim.x + threadIdx.x;
    if (s < NSLOT) {
        if (s < SHARED_BASE) {
            g_slot_token[s] = -1; g_slot_weight[s] = 0.f; g_slot_expert[s] = 0;
        } else {
            g_slot_token[s] = s - SHARED_BASE; g_slot_weight[s] = 1.f; g_slot_expert[s] = E_NUM;
        }
    }
    if (s < E_NUM) { g_counts[s] = 0; g_fill[s] = 0; }
}

static __global__ void router_kernel(const float* __restrict__ x,
                                     const float* __restrict__ rw) {
    int gwarp = (blockIdx.x * blockDim.x + threadIdx.x) >> 5;
    int lane  = threadIdx.x & 31;
    if (gwarp >= T_TOK) return;
    const float* xr = x + (size_t)gwarp * D_DIM;
    float acc[E_NUM];
#pragma unroll
    for (int e = 0; e < E_NUM; e++) acc[e] = 0.f;
    for (int d = lane; d < D_DIM; d += 32) {
        float xv = xr[d];
#pragma unroll
        for (int e = 0; e < E_NUM; e++) acc[e] += xv * rw[e * D_DIM + d];
    }
#pragma unroll
    for (int e = 0; e < E_NUM; e++)
#pragma unroll
        for (int o = 16; o > 0; o >>= 1)
            acc[e] += __shfl_xor_sync(0xFFFFFFFFu, acc[e], o);
    if (lane == 0) {
        int i1 = 0; float l1 = acc[0];
#pragma unroll
        for (int e = 1; e < E_NUM; e++) if (acc[e] > l1) { l1 = acc[e]; i1 = e; }
        int i2 = -1; float l2 = -INFINITY;
#pragma unroll
        for (int e = 0; e < E_NUM; e++)
            if (e != i1 && acc[e] > l2) { l2 = acc[e]; i2 = e; }
        float w1 = 1.f / (1.f + expf(l2 - l1));
        float w2 = 1.f - w1;
        g_tok_idx[gwarp * 2 + 0] = i1;  g_tok_idx[gwarp * 2 + 1] = i2;
        g_tok_w  [gwarp * 2 + 0] = w1;  g_tok_w  [gwarp * 2 + 1] = w2;
        atomicAdd(&g_counts[i1], 1);    atomicAdd(&g_counts[i2], 1);
    }
}

static __global__ void offsets_kernel() {
    if (blockIdx.x == 0 && threadIdx.x == 0) {
        int off = 0;
#pragma unroll
        for (int e = 0; e < E_NUM; e++) {
            g_aoff[e] = off;
            off = (off + g_counts[e] + 127) & ~127;
        }
    }
}

static __global__ void assign_kernel() {
    int t = blockIdx.x * blockDim.x + threadIdx.x;
    if (t >= T_TOK) return;
#pragma unroll
    for (int k = 0; k < 2; k++) {
        int   e = g_tok_idx[t * 2 + k];
        float w = g_tok_w  [t * 2 + k];
        int pos = atomicAdd(&g_fill[e], 1);
        int s   = g_aoff[e] + pos;
        g_slot_token[s] = t; g_slot_weight[s] = w; g_slot_expert[s] = e;
    }
}

static __global__ void zero_out_kernel(float4* __restrict__ out) {
    int i = blockIdx.x * blockDim.x + threadIdx.x;
    if (i < (T_TOK * D_DIM) / 4) out[i] = make_float4(0.f, 0.f, 0.f, 0.f);
}

// ---------------- fp16 mma.sync ragged GEMM, 128x256 tile, 64x64 warp tile ----
// IS_FC:  h = relu(gathered_x @ Wfc^T)^2 -> g_h (fp16)
// else:   out[tok] += w * (g_h @ Wproj^T)
template <int KDIM, bool IS_FC>
static __global__ void __launch_bounds__(256, 1)
moe_mma(float* __restrict__ outp)
{
    extern __shared__ __align__(16) char smem[];
    const uint32_t sb = smem_u32(smem);

    const int tid  = threadIdx.x;
    const int wid  = tid >> 5, lane = tid & 31;
    const int wm   = wid >> 2, wn = wid & 3;       // 2 x 4 warp grid, 64x64 tiles
    const int m0   = blockIdx.y * BM, n0 = blockIdx.x * BN;
    const int expert = g_slot_expert[m0];

    const __half *A, *B;
    if (IS_FC) {
        A = g_x;
        B = (expert < E_NUM) ? g_wfc + (size_t)expert * FF * D_DIM : g_sfc;
    } else {
        A = g_h;
        B = (expert < E_NUM) ? g_wpj + (size_t)expert * D_DIM * FF : g_spj;
    }

    // ---- loader mapping: thread t covers rows lr+32p, 16B col g ----
    // A: p = 0..3 (128 rows); B: p = 0..7 (256 rows)
    const int lr = tid >> 3;
    const int g  = tid & 7;
    const __half* aP[4];                // per-row base (gathered for FC)
    uint32_t asz[4];
#pragma unroll
    for (int p = 0; p < 4; p++) {
        int slot = m0 + lr + 32 * p;
        if (IS_FC) {
            int tok = g_slot_token[slot];
            asz[p] = (tok >= 0) ? 16u : 0u;
            aP[p]  = A + (size_t)(tok >= 0 ? tok : 0) * KDIM;
        } else {
            asz[p] = 16u;
            aP[p]  = A + (size_t)slot * KDIM;
        }
    }
    const __half* bBase = B + (size_t)(n0 + lr) * KDIM;   // + p*32*KDIM
    // swizzle column term is p-invariant ((lr+32p)&7 == lr&7)
    const uint32_t soff0 = (uint32_t)lr * 128
                         + (((uint32_t)g * 16) ^ (((uint32_t)lr & 7) * 16));

    // ---- ldmatrix lane addressing (p/mt-invariant swizzle) ----
    const uint32_t preA0 = (uint32_t)(wm * 64 + (lane & 15)) * 128;   // + mt*2048
    const uint32_t xvA   = ((uint32_t)lane & 7) * 16;
    const uint32_t cA    = ((uint32_t)lane >> 4) * 16;
    const uint32_t preB0 = (uint32_t)(wn * 64 + (lane & 7) + (((uint32_t)lane >> 4) << 3)) * 128;
    const uint32_t xvB   = ((uint32_t)lane & 7) * 16;
    const uint32_t cB    = (((uint32_t)lane >> 3) & 1) * 16;

    float acc[4][8][4];
#pragma unroll
    for (int mt = 0; mt < 4; mt++)
#pragma unroll
        for (int nt = 0; nt < 8; nt++)
#pragma unroll
            for (int j = 0; j < 4; j++) acc[mt][nt][j] = 0.f;

    auto issue_stage = [&](int kc) {
        const uint32_t bb = sb + (uint32_t)(kc % STAGES) * BUF_B;
        const int kb = kc * BK + g * 8;
#pragma unroll
        for (int p = 0; p < 4; p++)
            cp16(bb + A_OFF + soff0 + p * 4096, aP[p] + kb, asz[p]);
#pragma unroll
        for (int p = 0; p < 8; p++)
            cp16(bb + B_OFF + soff0 + p * 4096, bBase + (size_t)p * 32 * KDIM + kb, 16u);
    };

    auto mma_chunk = [&](uint32_t bb) {
#pragma unroll
        for (int kk = 0; kk < 4; kk++) {
            const uint32_t kb = (uint32_t)kk * 32;
            uint32_t ah[4][4], bh[8][2];
#pragma unroll
            for (int mt = 0; mt < 4; mt++)
                ldm_x4(bb + A_OFF + preA0 + mt * 2048 + ((cA + kb) ^ xvA), ah[mt]);
#pragma unroll
            for (int p = 0; p < 4; p++) {
                uint32_t t[4];
                ldm_x4(bb + B_OFF + preB0 + p * 2048 + ((cB + kb) ^ xvB), t);
                bh[2*p][0] = t[0]; bh[2*p][1] = t[1];
                bh[2*p+1][0] = t[2]; bh[2*p+1][1] = t[3];
            }
#pragma unroll
            for (int mt = 0; mt < 4; mt++)
#pragma unroll
                for (int nt = 0; nt < 8; nt++)
                    mma16816(acc[mt][nt], ah[mt], bh[nt]);
        }
    };

    const int NK = KDIM / BK;
#pragma unroll
    for (int s = 0; s < STAGES - 1; s++) {
        issue_stage(s);
        cp_commit();
    }
    for (int kc = 0; kc < NK; kc++) {
        cp_wait<STAGES - 2>();
        __syncthreads();
        if (kc + STAGES - 1 < NK) issue_stage(kc + STAGES - 1);
        cp_commit();
        mma_chunk(sb + (uint32_t)(kc % STAGES) * BUF_B);
    }

    // ---------------- epilogue ----------------
    const int qn = 2 * (lane & 3);
#pragma unroll
    for (int mt = 0; mt < 4; mt++) {
#pragma unroll
        for (int half = 0; half < 2; half++) {
            const int row  = wm * 64 + mt * 16 + (lane >> 2) + 8 * half;
            const int slot = m0 + row;
            if (IS_FC) {
                const size_t base = (size_t)slot * FF + n0 + wn * 64 + qn;
#pragma unroll
                for (int nt = 0; nt < 8; nt++) {
                    float v0 = fmaxf(acc[mt][nt][2 * half + 0], 0.f); v0 *= v0;
                    float v1 = fmaxf(acc[mt][nt][2 * half + 1], 0.f); v1 *= v1;
                    __half2 h = __floats2half2_rn(v0, v1);
                    *(uint32_t*)&g_h[base + nt * 8] = *reinterpret_cast<uint32_t*>(&h);
                }
            } else {
                const int   tok = g_slot_token[slot];
                const float w   = g_slot_weight[slot];
                if (tok >= 0 && w != 0.f) {
                    float* orow = outp + (size_t)tok * D_DIM + n0 + wn * 64 + qn;
#pragma unroll
                    for (int nt = 0; nt < 8; nt++) {
                        atomicAdd(orow + nt * 8 + 0, w * acc[mt][nt][2 * half + 0]);
                        atomicAdd(orow + nt * 8 + 1, w * acc[mt][nt][2 * half + 1]);
                    }
                }
            }
        }
    }
}

// ---------------- launch ----------------
extern "C" void kernel_launch(void* const* d_in, const int* in_sizes, int n_in,
                              void* d_out, int out_size) {
    const float* x     = (const float*)d_in[0];   // [4,2048,1024]
    const float* rw    = (const float*)d_in[1];   // [8,1024]
    const float* wfc   = (const float*)d_in[2];   // [8,4096,1024]
    const float* wproj = (const float*)d_in[3];   // [8,1024,4096]
    const float* sfc   = (const float*)d_in[4];   // [4096,1024]
    const float* sproj = (const float*)d_in[5];   // [1024,4096]
    float* out = (float*)d_out;                   // [4,2048,1024] fp32

    cudaFuncSetAttribute(moe_mma<D_DIM, true>,
                         cudaFuncAttributeMaxDynamicSharedMemorySize, SMEM_TOTAL);
    cudaFuncSetAttribute(moe_mma<FF, false>,
                         cudaFuncAttributeMaxDynamicSharedMemorySize, SMEM_TOTAL);

    __half *xh, *fh, *ph, *sh, *qh;
    cudaGetSymbolAddress((void**)&xh, g_x);
    cudaGetSymbolAddress((void**)&fh, g_wfc);
    cudaGetSymbolAddress((void**)&ph, g_wpj);
    cudaGetSymbolAddress((void**)&sh, g_sfc);
    cudaGetSymbolAddress((void**)&qh, g_spj);

    const int n4_x  = T_TOK * D_DIM / 4;
    const int n4_w  = E_NUM * FF * D_DIM / 4;
    const int n4_s  = FF * D_DIM / 4;
    cvt_hi2<<<(n4_x / 2 + 255) / 256, 256>>>((const float4*)x,     xh, n4_x);
    cvt_hi2<<<(n4_w / 2 + 255) / 256, 256>>>((const float4*)wfc,   fh, n4_w);
    cvt_hi2<<<(n4_w / 2 + 255) / 256, 256>>>((const float4*)wproj, ph, n4_w);
    cvt_hi2<<<(n4_s / 2 + 255) / 256, 256>>>((const float4*)sfc,   sh, n4_s);
    cvt_hi2<<<(n4_s / 2 + 255) / 256, 256>>>((const float4*)sproj, qh, n4_s);

    init_kernel<<<(NSLOT + 255) / 256, 256>>>();
    router_kernel<<<T_TOK / 8, 256>>>(x, rw);
    offsets_kernel<<<1, 32>>>();
    assign_kernel<<<T_TOK / 256, 256>>>();
    zero_out_kernel<<<(T_TOK * D_DIM / 4 + 255) / 256, 256>>>((float4*)out);

    // GEMM1: h = relu(gathered_x @ Wfc^T)^2
    moe_mma<D_DIM, true ><<<dim3(FF / BN,    NSLOT / BM), 256, SMEM_TOTAL>>>(nullptr);
    // GEMM2: out += w * (h @ Wproj^T)
    moe_mma<FF,    false><<<dim3(D_DIM / BN, NSLOT / BM), 256, SMEM_TOTAL>>>(out);
}

// round 10
// speedup vs baseline: 6.9770x; 1.0151x over previous
#include <cuda_runtime.h>
#include <cuda_fp16.h>
#include <cstdint>
#include <math.h>

// ---------------- problem constants ----------------
#define T_TOK   8192
#define D_DIM   1024
#define E_NUM   8
#define FF      4096
#define SHARED_BASE 17408
#define NSLOT       25600            // 200 * 128

#define BM  128
#define BN  256
#define BKS 128                       // superchunk: 128 halves = 2 x 64-col sub-tiles
// per-stage layout: A sub0 | A sub1 | B sub0 | B sub1
#define A_SUB 16384                   // 128 rows * 128 B
#define B_SUB 32768                   // 256 rows * 128 B
#define B_OFF (2 * A_SUB)             // 32768
#define BUF_B (2 * A_SUB + 2 * B_SUB) // 98304
#define STAGES 2
#define SMEM_TOTAL (STAGES * BUF_B)   // 196608

// ---------------- scratch (static __device__, no allocation) ----------------
static __device__ int   g_slot_token [NSLOT];
static __device__ float g_slot_weight[NSLOT];
static __device__ int   g_slot_expert[NSLOT];
static __device__ int   g_counts[E_NUM];
static __device__ int   g_fill  [E_NUM];
static __device__ int   g_aoff  [E_NUM];
static __device__ int   g_tok_idx[T_TOK * 2];
static __device__ float g_tok_w  [T_TOK * 2];

// fp16 single planes everywhere
static __device__ __half g_x  [(size_t)T_TOK * D_DIM];
static __device__ __half g_wfc[(size_t)E_NUM * FF * D_DIM];
static __device__ __half g_wpj[(size_t)E_NUM * D_DIM * FF];
static __device__ __half g_sfc[(size_t)FF * D_DIM];
static __device__ __half g_spj[(size_t)D_DIM * FF];
static __device__ __half g_h  [(size_t)NSLOT * FF];

// ---------------- helpers ----------------
__device__ __forceinline__ uint32_t smem_u32(const void* p) {
    uint32_t a;
    asm("{ .reg .u64 t; cvta.to.shared.u64 t, %1; cvt.u32.u64 %0, t; }" : "=r"(a) : "l"(p));
    return a;
}
__device__ __forceinline__ void ldm_x4(uint32_t addr, uint32_t r[4]) {
    asm volatile("ldmatrix.sync.aligned.m8n8.x4.shared.b16 {%0,%1,%2,%3}, [%4];"
                 : "=r"(r[0]), "=r"(r[1]), "=r"(r[2]), "=r"(r[3]) : "r"(addr));
}
__device__ __forceinline__ void mma16816(float d[4], const uint32_t a[4], const uint32_t b[2]) {
    asm volatile("mma.sync.aligned.m16n8k16.row.col.f32.f16.f16.f32 "
                 "{%0,%1,%2,%3}, {%4,%5,%6,%7}, {%8,%9}, {%0,%1,%2,%3};"
                 : "+f"(d[0]), "+f"(d[1]), "+f"(d[2]), "+f"(d[3])
                 : "r"(a[0]), "r"(a[1]), "r"(a[2]), "r"(a[3]), "r"(b[0]), "r"(b[1]));
}
__device__ __forceinline__ void cp16(uint32_t saddr, const void* gaddr, uint32_t src_sz) {
    asm volatile("cp.async.cg.shared.global [%0], [%1], 16, %2;"
                 :: "r"(saddr), "l"(gaddr), "r"(src_sz) : "memory");
}
__device__ __forceinline__ void cp_commit() {
    asm volatile("cp.async.commit_group;" ::: "memory");
}
template <int N>
__device__ __forceinline__ void cp_wait() {
    asm volatile("cp.async.wait_group %0;" :: "n"(N) : "memory");
}

// ---------------- pre-convert: fp32 -> fp16, 4 independent float4/thread ----
static __global__ void cvt_hi4(const float4* __restrict__ src,
                               __half* __restrict__ dst, int n4) {
    int base = (blockIdx.x * blockDim.x + threadIdx.x) * 4;
    if (base + 3 >= n4) {
        for (int j = 0; j < 4 && base + j < n4; j++) {
            float4 v = src[base + j];
            __half2 h0 = __floats2half2_rn(v.x, v.y);
            __half2 h1 = __floats2half2_rn(v.z, v.w);
            *(uint2*)(dst + 4 * (size_t)(base + j)) =
                make_uint2(*reinterpret_cast<uint32_t*>(&h0),
                           *reinterpret_cast<uint32_t*>(&h1));
        }
        return;
    }
    float4 v[4];
#pragma unroll
    for (int j = 0; j < 4; j++) v[j] = src[base + j];
#pragma unroll
    for (int j = 0; j < 4; j++) {
        __half2 h0 = __floats2half2_rn(v[j].x, v[j].y);
        __half2 h1 = __floats2half2_rn(v[j].z, v[j].w);
        *(uint2*)(dst + 4 * (size_t)(base + j)) =
            make_uint2(*reinterpret_cast<uint32_t*>(&h0),
                       *reinterpret_cast<uint32_t*>(&h1));
    }
}

// ---------------- routing kernels ----------------
static __global__ void init_kernel() {
    int s = blockIdx.x * blockDim.x + threadIdx.x;
    if (s < NSLOT) {
        if (s < SHARED_BASE) {
            g_slot_token[s] = -1; g_slot_weight[s] = 0.f; g_slot_expert[s] = 0;
        } else {
            g_slot_token[s] = s - SHARED_BASE; g_slot_weight[s] = 1.f; g_slot_expert[s] = E_NUM;
        }
    }
    if (s < E_NUM) { g_counts[s] = 0; g_fill[s] = 0; }
}

static __global__ void router_kernel(const float* __restrict__ x,
                                     const float* __restrict__ rw) {
    int gwarp = (blockIdx.x * blockDim.x + threadIdx.x) >> 5;
    int lane  = threadIdx.x & 31;
    if (gwarp >= T_TOK) return;
    const float* xr = x + (size_t)gwarp * D_DIM;
    float acc[E_NUM];
#pragma unroll
    for (int e = 0; e < E_NUM; e++) acc[e] = 0.f;
    for (int d = lane; d < D_DIM; d += 32) {
        float xv = xr[d];
#pragma unroll
        for (int e = 0; e < E_NUM; e++) acc[e] += xv * rw[e * D_DIM + d];
    }
#pragma unroll
    for (int e = 0; e < E_NUM; e++)
#pragma unroll
        for (int o = 16; o > 0; o >>= 1)
            acc[e] += __shfl_xor_sync(0xFFFFFFFFu, acc[e], o);
    if (lane == 0) {
        int i1 = 0; float l1 = acc[0];
#pragma unroll
        for (int e = 1; e < E_NUM; e++) if (acc[e] > l1) { l1 = acc[e]; i1 = e; }
        int i2 = -1; float l2 = -INFINITY;
#pragma unroll
        for (int e = 0; e < E_NUM; e++)
            if (e != i1 && acc[e] > l2) { l2 = acc[e]; i2 = e; }
        float w1 = 1.f / (1.f + expf(l2 - l1));
        float w2 = 1.f - w1;
        g_tok_idx[gwarp * 2 + 0] = i1;  g_tok_idx[gwarp * 2 + 1] = i2;
        g_tok_w  [gwarp * 2 + 0] = w1;  g_tok_w  [gwarp * 2 + 1] = w2;
        atomicAdd(&g_counts[i1], 1);    atomicAdd(&g_counts[i2], 1);
    }
}

static __global__ void offsets_kernel() {
    if (blockIdx.x == 0 && threadIdx.x == 0) {
        int off = 0;
#pragma unroll
        for (int e = 0; e < E_NUM; e++) {
            g_aoff[e] = off;
            off = (off + g_counts[e] + 127) & ~127;
        }
    }
}

static __global__ void assign_kernel() {
    int t = blockIdx.x * blockDim.x + threadIdx.x;
    if (t >= T_TOK) return;
#pragma unroll
    for (int k = 0; k < 2; k++) {
        int   e = g_tok_idx[t * 2 + k];
        float w = g_tok_w  [t * 2 + k];
        int pos = atomicAdd(&g_fill[e], 1);
        int s   = g_aoff[e] + pos;
        g_slot_token[s] = t; g_slot_weight[s] = w; g_slot_expert[s] = e;
    }
}

static __global__ void zero_out_kernel(float4* __restrict__ out) {
    int i = blockIdx.x * blockDim.x + threadIdx.x;
    if (i < (T_TOK * D_DIM) / 4) out[i] = make_float4(0.f, 0.f, 0.f, 0.f);
}

// ---------------- fp16 mma.sync ragged GEMM, 128x256 tile, 128-col superchunk
// IS_FC:  h = relu(gathered_x @ Wfc^T)^2 -> g_h (fp16)
// else:   out[tok] += w * (g_h @ Wproj^T)
template <int KDIM, bool IS_FC>
static __global__ void __launch_bounds__(256, 1)
moe_mma(float* __restrict__ outp)
{
    extern __shared__ __align__(16) char smem[];
    const uint32_t sb = smem_u32(smem);

    const int tid  = threadIdx.x;
    const int wid  = tid >> 5, lane = tid & 31;
    const int wm   = wid >> 2, wn = wid & 3;       // 2 x 4 warp grid, 64x64 tiles
    const int m0   = blockIdx.y * BM, n0 = blockIdx.x * BN;
    const int expert = g_slot_expert[m0];

    const __half *A, *B;
    if (IS_FC) {
        A = g_x;
        B = (expert < E_NUM) ? g_wfc + (size_t)expert * FF * D_DIM : g_sfc;
    } else {
        A = g_h;
        B = (expert < E_NUM) ? g_wpj + (size_t)expert * D_DIM * FF : g_spj;
    }

    // ---- loader mapping: thread t covers rows lr+32p, 16B col g ----
    const int lr = tid >> 3;
    const int g  = tid & 7;
    const __half* aP[4];
    uint32_t asz[4];
#pragma unroll
    for (int p = 0; p < 4; p++) {
        int slot = m0 + lr + 32 * p;
        if (IS_FC) {
            int tok = g_slot_token[slot];
            asz[p] = (tok >= 0) ? 16u : 0u;
            aP[p]  = A + (size_t)(tok >= 0 ? tok : 0) * KDIM;
        } else {
            asz[p] = 16u;
            aP[p]  = A + (size_t)slot * KDIM;
        }
    }
    const __half* bBase = B + (size_t)(n0 + lr) * KDIM;
    const uint32_t soff0 = (uint32_t)lr * 128
                         + (((uint32_t)g * 16) ^ (((uint32_t)lr & 7) * 16));

    // ---- ldmatrix lane addressing ----
    const uint32_t preA0 = (uint32_t)(wm * 64 + (lane & 15)) * 128;
    const uint32_t xvA   = ((uint32_t)lane & 7) * 16;
    const uint32_t cA    = ((uint32_t)lane >> 4) * 16;
    const uint32_t preB0 = (uint32_t)(wn * 64 + (lane & 7) + (((uint32_t)lane >> 4) << 3)) * 128;
    const uint32_t xvB   = ((uint32_t)lane & 7) * 16;
    const uint32_t cB    = (((uint32_t)lane >> 3) & 1) * 16;

    float acc[4][8][4];
#pragma unroll
    for (int mt = 0; mt < 4; mt++)
#pragma unroll
        for (int nt = 0; nt < 8; nt++)
#pragma unroll
            for (int j = 0; j < 4; j++) acc[mt][nt][j] = 0.f;

    // one superchunk = 128 K-cols = two 64-col sub-tiles
    auto issue_super = [&](int sc) {
        const uint32_t bb = sb + (uint32_t)(sc & 1) * BUF_B;
#pragma unroll
        for (int sub = 0; sub < 2; sub++) {
            const int kb = sc * BKS + sub * 64 + g * 8;
#pragma unroll
            for (int p = 0; p < 4; p++)
                cp16(bb + sub * A_SUB + soff0 + p * 4096, aP[p] + kb, asz[p]);
#pragma unroll
            for (int p = 0; p < 8; p++)
                cp16(bb + B_OFF + sub * B_SUB + soff0 + p * 4096,
                     bBase + (size_t)p * 32 * KDIM + kb, 16u);
        }
    };

    auto mma_super = [&](uint32_t bb) {
#pragma unroll
        for (int kk = 0; kk < 8; kk++) {
            const uint32_t aSub = bb + (kk >> 2) * A_SUB;
            const uint32_t bSub = bb + B_OFF + (kk >> 2) * B_SUB;
            const uint32_t kb = (uint32_t)(kk & 3) * 32;
            uint32_t ah[4][4], bh[8][2];
#pragma unroll
            for (int mt = 0; mt < 4; mt++)
                ldm_x4(aSub + preA0 + mt * 2048 + ((cA + kb) ^ xvA), ah[mt]);
#pragma unroll
            for (int p = 0; p < 4; p++) {
                uint32_t t[4];
                ldm_x4(bSub + preB0 + p * 2048 + ((cB + kb) ^ xvB), t);
                bh[2*p][0] = t[0]; bh[2*p][1] = t[1];
                bh[2*p+1][0] = t[2]; bh[2*p+1][1] = t[3];
            }
#pragma unroll
            for (int mt = 0; mt < 4; mt++)
#pragma unroll
                for (int nt = 0; nt < 8; nt++)
                    mma16816(acc[mt][nt], ah[mt], bh[nt]);
        }
    };

    const int NSC = KDIM / BKS;
    issue_super(0);
    cp_commit();
    for (int sc = 0; sc < NSC; sc++) {
        cp_wait<0>();                   // superchunk sc resident
        __syncthreads();                // visible to all; buffer sc-1 fully consumed
        if (sc + 1 < NSC) {
            issue_super(sc + 1);        // loads overlap the MMA block below
            cp_commit();
        }
        mma_super(sb + (uint32_t)(sc & 1) * BUF_B);
    }

    // ---------------- epilogue ----------------
    const int qn = 2 * (lane & 3);
#pragma unroll
    for (int mt = 0; mt < 4; mt++) {
#pragma unroll
        for (int half = 0; half < 2; half++) {
            const int row  = wm * 64 + mt * 16 + (lane >> 2) + 8 * half;
            const int slot = m0 + row;
            if (IS_FC) {
                const size_t base = (size_t)slot * FF + n0 + wn * 64 + qn;
#pragma unroll
                for (int nt = 0; nt < 8; nt++) {
                    float v0 = fmaxf(acc[mt][nt][2 * half + 0], 0.f); v0 *= v0;
                    float v1 = fmaxf(acc[mt][nt][2 * half + 1], 0.f); v1 *= v1;
                    __half2 h = __floats2half2_rn(v0, v1);
                    *(uint32_t*)&g_h[base + nt * 8] = *reinterpret_cast<uint32_t*>(&h);
                }
            } else {
                const int   tok = g_slot_token[slot];
                const float w   = g_slot_weight[slot];
                if (tok >= 0 && w != 0.f) {
                    float* orow = outp + (size_t)tok * D_DIM + n0 + wn * 64 + qn;
#pragma unroll
                    for (int nt = 0; nt < 8; nt++) {
                        atomicAdd(orow + nt * 8 + 0, w * acc[mt][nt][2 * half + 0]);
                        atomicAdd(orow + nt * 8 + 1, w * acc[mt][nt][2 * half + 1]);
                    }
                }
            }
        }
    }
}

// ---------------- launch ----------------
extern "C" void kernel_launch(void* const* d_in, const int* in_sizes, int n_in,
                              void* d_out, int out_size) {
    const float* x     = (const float*)d_in[0];   // [4,2048,1024]
    const float* rw    = (const float*)d_in[1];   // [8,1024]
    const float* wfc   = (const float*)d_in[2];   // [8,4096,1024]
    const float* wproj = (const float*)d_in[3];   // [8,1024,4096]
    const float* sfc   = (const float*)d_in[4];   // [4096,1024]
    const float* sproj = (const float*)d_in[5];   // [1024,4096]
    float* out = (float*)d_out;                   // [4,2048,1024] fp32

    cudaFuncSetAttribute(moe_mma<D_DIM, true>,
                         cudaFuncAttributeMaxDynamicSharedMemorySize, SMEM_TOTAL);
    cudaFuncSetAttribute(moe_mma<FF, false>,
                         cudaFuncAttributeMaxDynamicSharedMemorySize, SMEM_TOTAL);

    __half *xh, *fh, *ph, *sh, *qh;
    cudaGetSymbolAddress((void**)&xh, g_x);
    cudaGetSymbolAddress((void**)&fh, g_wfc);
    cudaGetSymbolAddress((void**)&ph, g_wpj);
    cudaGetSymbolAddress((void**)&sh, g_sfc);
    cudaGetSymbolAddress((void**)&qh, g_spj);

    const int n4_x  = T_TOK * D_DIM / 4;
    const int n4_w  = E_NUM * FF * D_DIM / 4;
    const int n4_s  = FF * D_DIM / 4;
    cvt_hi4<<<(n4_x / 4 + 255) / 256, 256>>>((const float4*)x,     xh, n4_x);
    cvt_hi4<<<(n4_w / 4 + 255) / 256, 256>>>((const float4*)wfc,   fh, n4_w);
    cvt_hi4<<<(n4_w / 4 + 255) / 256, 256>>>((const float4*)wproj, ph, n4_w);
    cvt_hi4<<<(n4_s / 4 + 255) / 256, 256>>>((const float4*)sfc,   sh, n4_s);
    cvt_hi4<<<(n4_s / 4 + 255) / 256, 256>>>((const float4*)sproj, qh, n4_s);

    init_kernel<<<(NSLOT + 255) / 256, 256>>>();
    router_kernel<<<T_TOK / 8, 256>>>(x, rw);
    offsets_kernel<<<1, 32>>>();
    assign_kernel<<<T_TOK / 256, 256>>>();
    zero_out_kernel<<<(T_TOK * D_DIM / 4 + 255) / 256, 256>>>((float4*)out);

    // GEMM1: h = relu(gathered_x @ Wfc^T)^2
    moe_mma<D_DIM, true ><<<dim3(FF / BN,    NSLOT / BM), 256, SMEM_TOTAL>>>(nullptr);
    // GEMM2: out += w * (h @ Wproj^T)
    moe_mma<FF,    false><<<dim3(D_DIM / BN, NSLOT / BM), 256, SMEM_TOTAL>>>(out);
}